// round 12
// baseline (speedup 1.0000x reference)
#include <cuda_runtime.h>
#include <cuda_fp16.h>
#include <cstdint>

// ---------------------------------------------------------------------------
// ChildSumTreeLSTM depth 17, D=H=128. R12: X-projections precomputed for
// internal nodes (g_X, bias folded); tlevel = 5 U-gemms with double-buffered
// B staging (4 syncs); leaf/gx use the same fp16 2-pass HMMA path, 2 CTAs/SM.
// ---------------------------------------------------------------------------

#define DEPTH   17
#define HH      128
#define NNODES  ((1 << (DEPTH + 1)) - 1)        // 262143
#define NINT    131071                           // internal nodes 0..131070
#define PITCH   136
#define GXN     16777216L                        // padded per-gate g_X stride

__device__ float g_h[33554304L];
__device__ float g_c[33554304L];
__device__ float g_X[4 * 16777216L];             // gates i,f,o,u (internal only)
// fp16 weight images, dense [k][n]. mats: 0..3 = W_i,W_f,W_o,W_u ; 4..7 = U_*
__device__ uint4 g_Wh[8][2048];

__device__ __forceinline__ float sigf(float v)  { return 1.0f / (1.0f + __expf(-v)); }
__device__ __forceinline__ float tanhx(float v) {
    float r; asm("tanh.approx.f32 %0, %1;" : "=f"(r) : "f"(v)); return r;
}
__device__ __forceinline__ uint32_t smem_u32(const void* p) {
    uint32_t a; asm("{ .reg .u64 t; cvta.to.shared.u64 t, %1; cvt.u32.u64 %0, t; }"
                    : "=r"(a) : "l"(p)); return a;
}
__device__ __forceinline__ void ldsm4(uint32_t& r0, uint32_t& r1, uint32_t& r2,
                                      uint32_t& r3, uint32_t a) {
    asm volatile("ldmatrix.sync.aligned.m8n8.x4.shared.b16 {%0,%1,%2,%3}, [%4];"
                 : "=r"(r0), "=r"(r1), "=r"(r2), "=r"(r3) : "r"(a));
}
__device__ __forceinline__ void ldsm4t(uint32_t& r0, uint32_t& r1, uint32_t& r2,
                                       uint32_t& r3, uint32_t a) {
    asm volatile("ldmatrix.sync.aligned.m8n8.x4.trans.shared.b16 {%0,%1,%2,%3}, [%4];"
                 : "=r"(r0), "=r"(r1), "=r"(r2), "=r"(r3) : "r"(a));
}
__device__ __forceinline__ void mmaH(float* c, uint32_t a0, uint32_t a1,
                                     uint32_t a2, uint32_t a3,
                                     uint32_t b0, uint32_t b1) {
    asm volatile("mma.sync.aligned.m16n8k16.row.col.f32.f16.f16.f32 "
                 "{%0,%1,%2,%3}, {%4,%5,%6,%7}, {%8,%9}, {%0,%1,%2,%3};"
                 : "+f"(c[0]), "+f"(c[1]), "+f"(c[2]), "+f"(c[3])
                 : "r"(a0), "r"(a1), "r"(a2), "r"(a3), "r"(b0), "r"(b1));
}
__device__ __forceinline__ void split2h(float a, float b, uint32_t& hi, uint32_t& lo) {
    __half2 h = __floats2half2_rn(a, b);
    float ra = a - __low2float(h);
    float rb = b - __high2float(h);
    __half2 l = __floats2half2_rn(ra, rb);
    hi = *(uint32_t*)&h; lo = *(uint32_t*)&l;
}

// fp16 2-pass GEMM: dacc[4][4] += (A_hi + A_lo) @ B. Warp: 16 rows x 32 cols.
__device__ __forceinline__ void gemm_H(float (*dacc)[4], uint32_t aH, uint32_t aL,
                                       uint32_t bB)
{
#pragma unroll
    for (int kc = 0; kc < 8; ++kc) {
        uint32_t ah0,ah1,ah2,ah3, al0,al1,al2,al3;
        ldsm4(ah0,ah1,ah2,ah3, aH + kc*32);
        ldsm4(al0,al1,al2,al3, aL + kc*32);
        uint32_t bp = bB + kc*(16*PITCH*2);
        uint32_t b0,b1,b2,b3, b4,b5,b6,b7;
        ldsm4t(b0,b1,b2,b3, bp);
        ldsm4t(b4,b5,b6,b7, bp + 32);
        mmaH(dacc[0], ah0,ah1,ah2,ah3, b0,b1);
        mmaH(dacc[1], ah0,ah1,ah2,ah3, b2,b3);
        mmaH(dacc[2], ah0,ah1,ah2,ah3, b4,b5);
        mmaH(dacc[3], ah0,ah1,ah2,ah3, b6,b7);
        mmaH(dacc[0], al0,al1,al2,al3, b0,b1);
        mmaH(dacc[1], al0,al1,al2,al3, b2,b3);
        mmaH(dacc[2], al0,al1,al2,al3, b4,b5);
        mmaH(dacc[3], al0,al1,al2,al3, b6,b7);
    }
}

__device__ __forceinline__ void ldB8(uint4* r, int mat, int tid) {
    const uint4* src = g_Wh[mat];
#pragma unroll
    for (int q = 0; q < 8; ++q) r[q] = src[tid + q*256];
}
__device__ __forceinline__ void stB8(__half* Bp, const uint4* r, int tid) {
#pragma unroll
    for (int q = 0; q < 8; ++q) {
        int i = tid + q*256, row = i >> 4, ch = i & 15;
        *(uint4*)(Bp + row*PITCH + ch*8) = r[q];
    }
}

__global__ void conv_w_kernel(
    const float* __restrict__ W_i, const float* __restrict__ W_f,
    const float* __restrict__ W_o, const float* __restrict__ W_u,
    const float* __restrict__ U_i, const float* __restrict__ U_f,
    const float* __restrict__ U_o, const float* __restrict__ U_u)
{
    const float* mats[8] = { W_i, W_f, W_o, W_u, U_i, U_f, U_o, U_u };
    const float* M = mats[blockIdx.x];
    __half* dst = (__half*)&g_Wh[blockIdx.x][0];
    for (int idx = threadIdx.x; idx < 16384; idx += blockDim.x)
        dst[idx] = __float2half(M[idx]);
}

__device__ __forceinline__ void conv_row_h(__half* dh, __half* dl,
                                           int row, int half,
                                           const float* __restrict__ s0,
                                           const float* __restrict__ s1)
{
#pragma unroll
    for (int i = 0; i < 16; ++i) {
        float4 v = *(const float4*)(s0 + i*4);
        if (s1) {
            float4 w = *(const float4*)(s1 + i*4);
            v.x += w.x; v.y += w.y; v.z += w.z; v.w += w.w;
        }
        uint32_t h0,l0,h1,l1;
        split2h(v.x,v.y,h0,l0); split2h(v.z,v.w,h1,l1);
        *(uint2*)(dh + row*PITCH + half + i*4) = make_uint2(h0,h1);
        *(uint2*)(dl + row*PITCH + half + i*4) = make_uint2(l0,l1);
    }
}

#define ZERO4 { _Pragma("unroll") for (int t = 0; t < 4; ++t) \
        { dacc[t][0]=0.f; dacc[t][1]=0.f; dacc[t][2]=0.f; dacc[t][3]=0.f; } }

// ---------------------------------------------------------------------------
// gx: X_g = x@W_g + b_g for internal nodes (0..131070). 32 nodes/block,
// double-buffered B. smem: Xh,Xl(32*PITCH) + B0,B1(128*PITCH) = 104448 B.
// ---------------------------------------------------------------------------
__global__ void __launch_bounds__(256, 2) gx_kernel(
    const float* __restrict__ x,
    const float* __restrict__ b_i, const float* __restrict__ b_f,
    const float* __restrict__ b_o, const float* __restrict__ b_u)
{
    constexpr int AS = 32 * PITCH;
    extern __shared__ __align__(16) __half sm[];
    __half* Xh = sm;
    __half* Xl = sm + AS;
    __half* B0 = sm + 2*AS;
    __half* B1 = sm + 2*AS + 128*PITCH;

    const int tid = threadIdx.x;
    const int w = tid >> 5, l = tid & 31;
    const int mg = w >> 2, nh = w & 3;
    const int lr = l & 15, lc = l >> 4;
    const int qr = l >> 2, qc2 = (l & 3) * 2;
    const long np = (long)blockIdx.x * 32;

    uint4 breg[8];
    ldB8(breg, 3, tid);                     // W_u
    if (tid < 64) {
        int row = tid >> 1, half = (tid & 1) * 64;
        conv_row_h(Xh, Xl, row, half, x + (np + row)*HH + half, nullptr);
    }
    stB8(B0, breg, tid);
    __syncthreads();

    const uint32_t a_off = (uint32_t)((16*mg + lr)*PITCH + lc*8)*2;
    const uint32_t b_off = (uint32_t)(lr*PITCH + nh*32 + lc*8)*2;
    const uint32_t xH = smem_u32(Xh)+a_off, xL = smem_u32(Xl)+a_off;
    const uint32_t bB0 = smem_u32(B0)+b_off, bB1 = smem_u32(B1)+b_off;

    const long n0 = np + 16*mg + qr, n1 = n0 + 8;
    const int cbase = nh*32 + qc2;
    const bool v0 = n0 < NINT, v1 = n1 < NINT;

    float dacc[4][4];
#define STORE_X(G, BIAS) { float* out = g_X + (long)(G)*GXN;                   \
    _Pragma("unroll") for (int t = 0; t < 4; ++t) {                            \
        int c = cbase + t*8;                                                   \
        float2 b = *(const float2*)((BIAS) + c);                               \
        if (v0) *(float2*)(out + n0*HH + c) =                                  \
            make_float2(dacc[t][0]+b.x, dacc[t][1]+b.y);                       \
        if (v1) *(float2*)(out + n1*HH + c) =                                  \
            make_float2(dacc[t][2]+b.x, dacc[t][3]+b.y);                       \
    } }

    ldB8(breg, 0, tid); stB8(B1, breg, tid);           // W_i -> B1
    ZERO4; gemm_H(dacc, xH, xL, bB0);                  // x @ W_u
    STORE_X(3, b_u);
    __syncthreads();

    ldB8(breg, 1, tid); stB8(B0, breg, tid);           // W_f -> B0
    ZERO4; gemm_H(dacc, xH, xL, bB1);                  // x @ W_i
    STORE_X(0, b_i);
    __syncthreads();

    ldB8(breg, 2, tid); stB8(B1, breg, tid);           // W_o -> B1
    ZERO4; gemm_H(dacc, xH, xL, bB0);                  // x @ W_f
    STORE_X(1, b_f);
    __syncthreads();

    ZERO4; gemm_H(dacc, xH, xL, bB1);                  // x @ W_o
    STORE_X(2, b_o);
#undef STORE_X
}

// ---------------------------------------------------------------------------
// Leaf: 32 leaves/block, double-buffered B, gates u,i,o.
// ---------------------------------------------------------------------------
__global__ void __launch_bounds__(256, 2) leaf_kernel(
    const float* __restrict__ x,
    const float* __restrict__ b_i, const float* __restrict__ b_o,
    const float* __restrict__ b_u)
{
    constexpr int AS = 32 * PITCH;
    extern __shared__ __align__(16) __half sm[];
    __half* Xh = sm;
    __half* Xl = sm + AS;
    __half* B0 = sm + 2*AS;
    __half* B1 = sm + 2*AS + 128*PITCH;

    const int tid = threadIdx.x;
    const int w = tid >> 5, l = tid & 31;
    const int mg = w >> 2, nh = w & 3;
    const int lr = l & 15, lc = l >> 4;
    const int qr = l >> 2, qc2 = (l & 3) * 2;
    const long np = (long)NINT + (long)blockIdx.x * 32;   // leaves 131071..262142

    uint4 breg[8];
    ldB8(breg, 3, tid);                     // W_u
    if (tid < 64) {
        int row = tid >> 1, half = (tid & 1) * 64;
        conv_row_h(Xh, Xl, row, half, x + (np + row)*HH + half, nullptr);
    }
    stB8(B0, breg, tid);
    __syncthreads();

    const uint32_t a_off = (uint32_t)((16*mg + lr)*PITCH + lc*8)*2;
    const uint32_t b_off = (uint32_t)(lr*PITCH + nh*32 + lc*8)*2;
    const uint32_t xH = smem_u32(Xh)+a_off, xL = smem_u32(Xl)+a_off;
    const uint32_t bB0 = smem_u32(B0)+b_off, bB1 = smem_u32(B1)+b_off;

    const long n0 = np + 16*mg + qr, n1 = n0 + 8;
    const int cbase = nh*32 + qc2;

    float dacc[4][4], cc[4][4];

    ldB8(breg, 0, tid); stB8(B1, breg, tid);           // W_i -> B1
    ZERO4; gemm_H(dacc, xH, xL, bB0);                  // x @ W_u
#pragma unroll
    for (int t = 0; t < 4; ++t) {
        float2 b = *(const float2*)(b_u + cbase + t*8);
        cc[t][0]=tanhx(dacc[t][0]+b.x); cc[t][1]=tanhx(dacc[t][1]+b.y);
        cc[t][2]=tanhx(dacc[t][2]+b.x); cc[t][3]=tanhx(dacc[t][3]+b.y);
    }
    __syncthreads();

    ldB8(breg, 2, tid); stB8(B0, breg, tid);           // W_o -> B0
    ZERO4; gemm_H(dacc, xH, xL, bB1);                  // x @ W_i
#pragma unroll
    for (int t = 0; t < 4; ++t) {
        float2 b = *(const float2*)(b_i + cbase + t*8);
        cc[t][0]*=sigf(dacc[t][0]+b.x); cc[t][1]*=sigf(dacc[t][1]+b.y);
        cc[t][2]*=sigf(dacc[t][2]+b.x); cc[t][3]*=sigf(dacc[t][3]+b.y);
    }
    __syncthreads();

    ZERO4; gemm_H(dacc, xH, xL, bB0);                  // x @ W_o
#pragma unroll
    for (int t = 0; t < 4; ++t) {
        int c = cbase + t*8;
        float2 b = *(const float2*)(b_o + c);
        float h0 = sigf(dacc[t][0]+b.x)*tanhx(cc[t][0]);
        float h1 = sigf(dacc[t][1]+b.y)*tanhx(cc[t][1]);
        float h2 = sigf(dacc[t][2]+b.x)*tanhx(cc[t][2]);
        float h3 = sigf(dacc[t][3]+b.y)*tanhx(cc[t][3]);
        *(float2*)(g_c + n0*HH + c) = make_float2(cc[t][0], cc[t][1]);
        *(float2*)(g_c + n1*HH + c) = make_float2(cc[t][2], cc[t][3]);
        *(float2*)(g_h + n0*HH + c) = make_float2(h0, h1);
        *(float2*)(g_h + n1*HH + c) = make_float2(h2, h3);
    }
}

// ---------------------------------------------------------------------------
// Tensor level kernel: 32 parents/block, 5 U-gemms, 4 syncs, double-buffer B.
// A slots: SUM(h0+h1), S1(h1). X projections come from g_X (bias folded).
// smem: 4*32*PITCH + 2*128*PITCH = 104448 B -> 2 CTAs/SM.
// ---------------------------------------------------------------------------
__global__ void __launch_bounds__(256, 2) tlevel_kernel(int sl)
{
    constexpr int AS = 32 * PITCH;
    extern __shared__ __align__(16) __half sm[];
    __half* SUh = sm;
    __half* SUl = sm + AS;
    __half* S1h = sm + 2*AS;
    __half* S1l = sm + 3*AS;
    __half* B0  = sm + 4*AS;
    __half* B1  = sm + 4*AS + 128*PITCH;

    const int tid = threadIdx.x;
    const int w = tid >> 5, l = tid & 31;
    const int mg = w >> 2, nh = w & 3;
    const int lr = l & 15, lc = l >> 4;
    const int qr = l >> 2, qc2 = (l & 3) * 2;

    const long np = (long)sl + (long)blockIdx.x * 32;
    const long cb = 2*np + 1;

    uint4 breg[8];
    ldB8(breg, 7, tid);                     // U_u
    if (tid < 128) {
        int slot = tid >> 6;                // 0=SUM, 1=S1
        int row  = (tid & 63) >> 1;
        int half = (tid & 1) * 64;
        if (slot == 0)
            conv_row_h(SUh, SUl, row, half, g_h + (cb + 2*row)*HH + half,
                                            g_h + (cb + 2*row + 1)*HH + half);
        else
            conv_row_h(S1h, S1l, row, half, g_h + (cb + 2*row + 1)*HH + half, nullptr);
    }
    stB8(B0, breg, tid);
    __syncthreads();

    const uint32_t a_off = (uint32_t)((16*mg + lr)*PITCH + lc*8)*2;
    const uint32_t b_off = (uint32_t)(lr*PITCH + nh*32 + lc*8)*2;
    const uint32_t suH = smem_u32(SUh)+a_off, suL = smem_u32(SUl)+a_off;
    const uint32_t s1H = smem_u32(S1h)+a_off, s1L = smem_u32(S1l)+a_off;
    const uint32_t bB0 = smem_u32(B0)+b_off,  bB1 = smem_u32(B1)+b_off;

    const long n0 = np + 16*mg + qr, n1 = n0 + 8;
    const int cbase = nh*32 + qc2;

    float dacc[4][4], cc[4][4];

#define LDX(DST0, DST1, G) { const float* gx = g_X + (long)(G)*GXN;            \
    _Pragma("unroll") for (int t = 0; t < 4; ++t) {                            \
        int c = cbase + t*8;                                                   \
        DST0[t] = *(const float2*)(gx + n0*HH + c);                            \
        DST1[t] = *(const float2*)(gx + n1*HH + c);                            \
    } }

    // ---- u: SUM @ U_u ----
    float2 xg0[4], xg1[4];
    LDX(xg0, xg1, 3);
    ldB8(breg, 4, tid); stB8(B1, breg, tid);           // U_i -> B1
    ZERO4; gemm_H(dacc, suH, suL, bB0);
#pragma unroll
    for (int t = 0; t < 4; ++t) {
        cc[t][0]=tanhx(dacc[t][0]+xg0[t].x); cc[t][1]=tanhx(dacc[t][1]+xg0[t].y);
        cc[t][2]=tanhx(dacc[t][2]+xg1[t].x); cc[t][3]=tanhx(dacc[t][3]+xg1[t].y);
    }
    __syncthreads();

    // ---- i: SUM @ U_i ----
    LDX(xg0, xg1, 0);
    ldB8(breg, 5, tid); stB8(B0, breg, tid);           // U_f -> B0
    ZERO4; gemm_H(dacc, suH, suL, bB1);
#pragma unroll
    for (int t = 0; t < 4; ++t) {
        cc[t][0]*=sigf(dacc[t][0]+xg0[t].x); cc[t][1]*=sigf(dacc[t][1]+xg0[t].y);
        cc[t][2]*=sigf(dacc[t][2]+xg1[t].x); cc[t][3]*=sigf(dacc[t][3]+xg1[t].y);
    }
    __syncthreads();

    // ---- f: G1 = S1 @ U_f ; f0 via Gsum - G1 ----
    float2 xf0[4], xf1[4];
    LDX(xf0, xf1, 1);
    ldB8(breg, 6, tid); stB8(B1, breg, tid);           // U_o -> B1
    ZERO4; gemm_H(dacc, s1H, s1L, bB0);                // G1 = h1 @ U_f
#pragma unroll
    for (int t = 0; t < 4; ++t) {                      // f1 with child1 cell
        int c = cbase + t*8;
        float2 ca = *(const float2*)(g_c + (2*n0+2)*HH + c);
        float2 cbv = *(const float2*)(g_c + (2*n1+2)*HH + c);
        cc[t][0]+=sigf(dacc[t][0]+xf0[t].x)*ca.x;
        cc[t][1]+=sigf(dacc[t][1]+xf0[t].y)*ca.y;
        cc[t][2]+=sigf(dacc[t][2]+xf1[t].x)*cbv.x;
        cc[t][3]+=sigf(dacc[t][3]+xf1[t].y)*cbv.y;
        dacc[t][0]=-dacc[t][0]; dacc[t][1]=-dacc[t][1];
        dacc[t][2]=-dacc[t][2]; dacc[t][3]=-dacc[t][3];
    }
    gemm_H(dacc, suH, suL, bB0);                       // Gsum - G1 = h0 @ U_f
#pragma unroll
    for (int t = 0; t < 4; ++t) {                      // f0 with child0 cell
        int c = cbase + t*8;
        float2 ca = *(const float2*)(g_c + (2*n0+1)*HH + c);
        float2 cbv = *(const float2*)(g_c + (2*n1+1)*HH + c);
        cc[t][0]+=sigf(dacc[t][0]+xf0[t].x)*ca.x;
        cc[t][1]+=sigf(dacc[t][1]+xf0[t].y)*ca.y;
        cc[t][2]+=sigf(dacc[t][2]+xf1[t].x)*cbv.x;
        cc[t][3]+=sigf(dacc[t][3]+xf1[t].y)*cbv.y;
    }
    __syncthreads();

    // ---- o: SUM @ U_o + store ----
    LDX(xg0, xg1, 2);
    ZERO4; gemm_H(dacc, suH, suL, bB1);
#pragma unroll
    for (int t = 0; t < 4; ++t) {
        int c = cbase + t*8;
        float h0 = sigf(dacc[t][0]+xg0[t].x)*tanhx(cc[t][0]);
        float h1 = sigf(dacc[t][1]+xg0[t].y)*tanhx(cc[t][1]);
        float h2 = sigf(dacc[t][2]+xg1[t].x)*tanhx(cc[t][2]);
        float h3 = sigf(dacc[t][3]+xg1[t].y)*tanhx(cc[t][3]);
        *(float2*)(g_c + n0*HH + c) = make_float2(cc[t][0], cc[t][1]);
        *(float2*)(g_c + n1*HH + c) = make_float2(cc[t][2], cc[t][3]);
        *(float2*)(g_h + n0*HH + c) = make_float2(h0, h1);
        *(float2*)(g_h + n1*HH + c) = make_float2(h2, h3);
    }
#undef LDX
}

// ---------------------------------------------------------------------------
// Small levels (nl < 32): one parent/block, 512 threads, 5 U matvecs;
// X projections from g_X (bias folded).
// ---------------------------------------------------------------------------
__global__ void __launch_bounds__(512) small_level_kernel(
    int sl,
    const float* __restrict__ U_i, const float* __restrict__ U_f,
    const float* __restrict__ U_o, const float* __restrict__ U_u)
{
    extern __shared__ float smf[];
    float* hs   = smf;              // [h~ | h0 | h1] x 128
    float* part = smf + 384;        // [5][4][128]

    const int t = threadIdx.x;
    const long node = sl + blockIdx.x;
    const long ch0  = 2*node + 1;

    if (t < 128) {
        float h0 = g_h[ch0*HH + t];
        float h1 = g_h[(ch0+1)*HH + t];
        hs[128+t] = h0; hs[256+t] = h1; hs[t] = h0 + h1;
    }
    __syncthreads();

    const int col = t & 127;
    const int q   = t >> 7;
    const int kb  = q * 32;

#define JOB(J, S, M) { float av = 0.f; const float* s = hs + (S)*128;          \
        _Pragma("unroll 8")                                                    \
        for (int k = 0; k < 32; ++k) av += s[kb+k] * (M)[(kb+k)*HH + col];     \
        part[((J)*4 + q)*128 + col] = av; }
    JOB(0, 0, U_i) JOB(1, 0, U_o) JOB(2, 0, U_u)
    JOB(3, 1, U_f) JOB(4, 2, U_f)
#undef JOB
    __syncthreads();

    if (t < 128) {
#define SUMP(J) (part[((J)*4+0)*128+t] + part[((J)*4+1)*128+t] + \
                 part[((J)*4+2)*128+t] + part[((J)*4+3)*128+t])
        float yi  = SUMP(0), yo = SUMP(1), yu = SUMP(2);
        float yf0 = SUMP(3), yf1 = SUMP(4);
#undef SUMP
        long e = node*HH + t;
        float xi  = g_X[0*GXN + e];
        float xfv = g_X[1*GXN + e];
        float xo  = g_X[2*GXN + e];
        float xu  = g_X[3*GXN + e];
        float c = sigf(xi+yi)*tanhx(xu+yu)
                + sigf(xfv+yf0)*g_c[ch0*HH+t] + sigf(xfv+yf1)*g_c[(ch0+1)*HH+t];
        g_c[e] = c;
        g_h[e] = sigf(xo+yo)*tanhx(c);
    }
}

__global__ void out_kernel(float* __restrict__ out)
{
    int t = threadIdx.x;
    out[t] = (t < 128) ? g_h[t] : g_c[t - 128];
}

// ---------------------------------------------------------------------------
extern "C" void kernel_launch(void* const* d_in, const int* in_sizes, int n_in,
                              void* d_out, int out_size)
{
    const float* x   = (const float*)d_in[0];
    const float* W_i = (const float*)d_in[1];
    const float* b_i = (const float*)d_in[2];
    const float* U_i = (const float*)d_in[3];
    const float* W_f = (const float*)d_in[4];
    const float* b_f = (const float*)d_in[5];
    const float* U_f = (const float*)d_in[6];
    const float* W_o = (const float*)d_in[7];
    const float* b_o = (const float*)d_in[8];
    const float* U_o = (const float*)d_in[9];
    const float* W_u = (const float*)d_in[10];
    const float* b_u = (const float*)d_in[11];
    const float* U_u = (const float*)d_in[12];

    const int SMEM = (4*32*PITCH + 2*128*PITCH) * 2;    // 104448
    const int SMEM_S = (384 + 5*4*128) * 4;             // 11776
    cudaFuncSetAttribute(gx_kernel,     cudaFuncAttributeMaxDynamicSharedMemorySize, SMEM);
    cudaFuncSetAttribute(leaf_kernel,   cudaFuncAttributeMaxDynamicSharedMemorySize, SMEM);
    cudaFuncSetAttribute(tlevel_kernel, cudaFuncAttributeMaxDynamicSharedMemorySize, SMEM);
    cudaFuncSetAttribute(small_level_kernel, cudaFuncAttributeMaxDynamicSharedMemorySize, SMEM_S);

    conv_w_kernel<<<8, 256>>>(W_i, W_f, W_o, W_u, U_i, U_f, U_o, U_u);

    // X projections for internal nodes (0..131070); 4096 blocks cover 131072
    gx_kernel<<<(NINT + 31) / 32, 256, SMEM>>>(x, b_i, b_f, b_o, b_u);

    // leaves 131071..262142 = 131072 nodes
    leaf_kernel<<<131072 / 32, 256, SMEM>>>(x, b_i, b_o, b_u);

    for (int l = DEPTH - 1; l >= 0; --l) {
        int nl = 1 << l;
        int sl = nl - 1;
        if (nl >= 32)
            tlevel_kernel<<<nl / 32, 256, SMEM>>>(sl);
        else
            small_level_kernel<<<nl, 512, SMEM_S>>>(sl, U_i, U_f, U_o, U_u);
    }

    out_kernel<<<1, 256>>>((float*)d_out);
}

// round 13
// speedup vs baseline: 1.0804x; 1.0804x over previous
#include <cuda_runtime.h>
#include <cuda_fp16.h>
#include <cstdint>

// ---------------------------------------------------------------------------
// ChildSumTreeLSTM depth 17, D=H=128. R13: R11 structure (fp16 2-pass HMMA,
// in-level X gemms, 32 parents/block, 2 CTAs/SM) + XOR-swizzled smem (no pad)
// enabling double-buffered B staging: 8 syncs/block instead of 16, all
// weight-staging LDG latency hidden behind MMA work.
// ---------------------------------------------------------------------------

#define DEPTH   17
#define HH      128
#define NNODES  ((1 << (DEPTH + 1)) - 1)
#define NLEAF0  131071L                          // first leaf node
#define ASLOT   8192                             // 32 rows x 256 B
#define BSLOT   32768                            // 128 rows x 256 B

__device__ float g_h[33554304L];
__device__ float g_c[33554304L];
// fp16 weight images, dense [k][n]. mats: 0..3 = W_i,W_f,W_o,W_u ; 4..7 = U_*
__device__ uint4 g_Wh[8][2048];

__device__ __forceinline__ float sigf(float v)  { return 1.0f / (1.0f + __expf(-v)); }
__device__ __forceinline__ float tanhx(float v) {
    float r; asm("tanh.approx.f32 %0, %1;" : "=f"(r) : "f"(v)); return r;
}
__device__ __forceinline__ uint32_t smem_u32(const void* p) {
    uint32_t a; asm("{ .reg .u64 t; cvta.to.shared.u64 t, %1; cvt.u32.u64 %0, t; }"
                    : "=r"(a) : "l"(p)); return a;
}
__device__ __forceinline__ void ldsm4(uint32_t& r0, uint32_t& r1, uint32_t& r2,
                                      uint32_t& r3, uint32_t a) {
    asm volatile("ldmatrix.sync.aligned.m8n8.x4.shared.b16 {%0,%1,%2,%3}, [%4];"
                 : "=r"(r0), "=r"(r1), "=r"(r2), "=r"(r3) : "r"(a));
}
__device__ __forceinline__ void ldsm4t(uint32_t& r0, uint32_t& r1, uint32_t& r2,
                                       uint32_t& r3, uint32_t a) {
    asm volatile("ldmatrix.sync.aligned.m8n8.x4.trans.shared.b16 {%0,%1,%2,%3}, [%4];"
                 : "=r"(r0), "=r"(r1), "=r"(r2), "=r"(r3) : "r"(a));
}
__device__ __forceinline__ void mmaH(float* c, uint32_t a0, uint32_t a1,
                                     uint32_t a2, uint32_t a3,
                                     uint32_t b0, uint32_t b1) {
    asm volatile("mma.sync.aligned.m16n8k16.row.col.f32.f16.f16.f32 "
                 "{%0,%1,%2,%3}, {%4,%5,%6,%7}, {%8,%9}, {%0,%1,%2,%3};"
                 : "+f"(c[0]), "+f"(c[1]), "+f"(c[2]), "+f"(c[3])
                 : "r"(a0), "r"(a1), "r"(a2), "r"(a3), "r"(b0), "r"(b1));
}
__device__ __forceinline__ void split2h(float a, float b, uint32_t& hi, uint32_t& lo) {
    __half2 h = __floats2half2_rn(a, b);
    float ra = a - __low2float(h);
    float rb = b - __high2float(h);
    __half2 l = __floats2half2_rn(ra, rb);
    hi = *(uint32_t*)&h; lo = *(uint32_t*)&l;
}

// swizzle: chunk bits[4:6] ^= row bits[8:10] (rows are 256 B)
#define SWZ(o) ((o) ^ ((((o) >> 8) & 7u) << 4))

// ---------------------------------------------------------------------------
// fp16 2-pass GEMM on swizzled smem. la/lb: per-lane logical byte offsets;
// sx = (lr&7)<<4 (lane-constant swizzle XOR — row&7 invariant across kc).
// ---------------------------------------------------------------------------
__device__ __forceinline__ void gemm_H(float (*dacc)[4],
    uint32_t aHb, uint32_t aLb, uint32_t bBb,
    uint32_t la, uint32_t lb, uint32_t sx)
{
#pragma unroll
    for (int kc = 0; kc < 8; ++kc) {
        uint32_t ao  = (la + kc*32) ^ sx;
        uint32_t bo0 = (lb + kc*4096) ^ sx;
        uint32_t bo1 = (lb + kc*4096 + 32) ^ sx;
        uint32_t ah0,ah1,ah2,ah3, al0,al1,al2,al3;
        ldsm4(ah0,ah1,ah2,ah3, aHb + ao);
        ldsm4(al0,al1,al2,al3, aLb + ao);
        uint32_t b0,b1,b2,b3, b4,b5,b6,b7;
        ldsm4t(b0,b1,b2,b3, bBb + bo0);
        ldsm4t(b4,b5,b6,b7, bBb + bo1);
        mmaH(dacc[0], ah0,ah1,ah2,ah3, b0,b1);
        mmaH(dacc[1], ah0,ah1,ah2,ah3, b2,b3);
        mmaH(dacc[2], ah0,ah1,ah2,ah3, b4,b5);
        mmaH(dacc[3], ah0,ah1,ah2,ah3, b6,b7);
        mmaH(dacc[0], al0,al1,al2,al3, b0,b1);
        mmaH(dacc[1], al0,al1,al2,al3, b2,b3);
        mmaH(dacc[2], al0,al1,al2,al3, b4,b5);
        mmaH(dacc[3], al0,al1,al2,al3, b6,b7);
    }
}

// B staging: load to regs (8 uint4), store swizzled
__device__ __forceinline__ void ldB8(uint4* r, int mat, int tid) {
    const uint4* src = g_Wh[mat];
#pragma unroll
    for (int q = 0; q < 8; ++q) r[q] = src[tid + q*256];
}
__device__ __forceinline__ void stB8(char* Bp, const uint4* r, int tid) {
#pragma unroll
    for (int q = 0; q < 8; ++q) {
        uint32_t i  = (uint32_t)(tid + q*256);
        uint32_t lg = ((i >> 4) << 8) | ((i & 15u) << 4);
        *(uint4*)(Bp + SWZ(lg)) = r[q];
    }
}

__global__ void conv_w_kernel(
    const float* __restrict__ W_i, const float* __restrict__ W_f,
    const float* __restrict__ W_o, const float* __restrict__ W_u,
    const float* __restrict__ U_i, const float* __restrict__ U_f,
    const float* __restrict__ U_o, const float* __restrict__ U_u)
{
    const float* mats[8] = { W_i, W_f, W_o, W_u, U_i, U_f, U_o, U_u };
    const float* M = mats[blockIdx.x];
    __half* dst = (__half*)&g_Wh[blockIdx.x][0];
    for (int idx = threadIdx.x; idx < 16384; idx += blockDim.x)
        dst[idx] = __float2half(M[idx]);
}

// convert one fp32 row-half (opt. pair sum) into fp16 hi/lo swizzled smem
__device__ __forceinline__ void conv_row_h(char* dh, char* dl,
                                           int row, int half,
                                           const float* __restrict__ s0,
                                           const float* __restrict__ s1)
{
#pragma unroll
    for (int i = 0; i < 16; ++i) {
        float4 v = *(const float4*)(s0 + i*4);
        if (s1) {
            float4 w = *(const float4*)(s1 + i*4);
            v.x += w.x; v.y += w.y; v.z += w.z; v.w += w.w;
        }
        uint32_t h0,l0,h1,l1;
        split2h(v.x,v.y,h0,l0); split2h(v.z,v.w,h1,l1);
        uint32_t lg = (uint32_t)(row*256 + (half + i*4)*2);
        *(uint2*)(dh + SWZ(lg)) = make_uint2(h0,h1);
        *(uint2*)(dl + SWZ(lg)) = make_uint2(l0,l1);
    }
}

#define ZERO4 { _Pragma("unroll") for (int t = 0; t < 4; ++t) \
        { dacc[t][0]=0.f; dacc[t][1]=0.f; dacc[t][2]=0.f; dacc[t][3]=0.f; } }

// ---------------------------------------------------------------------------
// Leaf: 32 leaves/block, double-buffered B, 3 syncs. Gates u,i,o from x@W.
// smem: Xh,Xl (8 KB) + B0,B1 (32 KB) = 81920 B -> 2 CTAs/SM.
// ---------------------------------------------------------------------------
__global__ void __launch_bounds__(256, 2) leaf_kernel(
    const float* __restrict__ x,
    const float* __restrict__ b_i, const float* __restrict__ b_o,
    const float* __restrict__ b_u)
{
    extern __shared__ __align__(16) char sm[];
    char* Xh = sm;
    char* Xl = sm + ASLOT;
    char* B0 = sm + 2*ASLOT;
    char* B1 = sm + 2*ASLOT + BSLOT;

    const int tid = threadIdx.x;
    const int w = tid >> 5, l = tid & 31;
    const int mg = w >> 2, nh = w & 3;
    const int lr = l & 15, lc = l >> 4;
    const int qr = l >> 2, qc2 = (l & 3) * 2;
    const long np = NLEAF0 + (long)blockIdx.x * 32;

    uint4 breg[8];
    ldB8(breg, 3, tid);                     // W_u
    if (tid < 64) {
        int row = tid >> 1, half = (tid & 1) * 64;
        conv_row_h(Xh, Xl, row, half, x + (np + row)*HH + half, nullptr);
    }
    stB8(B0, breg, tid);
    ldB8(breg, 0, tid);                     // W_i
    __syncthreads();

    const uint32_t la = (uint32_t)((16*mg + lr)*256 + lc*16);
    const uint32_t lb = (uint32_t)(lr*256 + nh*64 + lc*16);
    const uint32_t sx = (uint32_t)(lr & 7) << 4;
    const uint32_t xH = smem_u32(Xh), xL = smem_u32(Xl);
    const uint32_t bb0 = smem_u32(B0), bb1 = smem_u32(B1);

    const long n0 = np + 16*mg + qr, n1 = n0 + 8;
    const int cbase = nh*32 + qc2;

    float dacc[4][4], cc[4][4];

    ZERO4; gemm_H(dacc, xH, xL, bb0, la, lb, sx);     // x @ W_u
    stB8(B1, breg, tid);
    ldB8(breg, 2, tid);                     // W_o
#pragma unroll
    for (int t = 0; t < 4; ++t) {
        float2 b = *(const float2*)(b_u + cbase + t*8);
        cc[t][0]=tanhx(dacc[t][0]+b.x); cc[t][1]=tanhx(dacc[t][1]+b.y);
        cc[t][2]=tanhx(dacc[t][2]+b.x); cc[t][3]=tanhx(dacc[t][3]+b.y);
    }
    __syncthreads();

    ZERO4; gemm_H(dacc, xH, xL, bb1, la, lb, sx);     // x @ W_i
    stB8(B0, breg, tid);
#pragma unroll
    for (int t = 0; t < 4; ++t) {
        float2 b = *(const float2*)(b_i + cbase + t*8);
        cc[t][0]*=sigf(dacc[t][0]+b.x); cc[t][1]*=sigf(dacc[t][1]+b.y);
        cc[t][2]*=sigf(dacc[t][2]+b.x); cc[t][3]*=sigf(dacc[t][3]+b.y);
    }
    __syncthreads();

    ZERO4; gemm_H(dacc, xH, xL, bb0, la, lb, sx);     // x @ W_o
#pragma unroll
    for (int t = 0; t < 4; ++t) {
        int c = cbase + t*8;
        float2 b = *(const float2*)(b_o + c);
        float h0 = sigf(dacc[t][0]+b.x)*tanhx(cc[t][0]);
        float h1 = sigf(dacc[t][1]+b.y)*tanhx(cc[t][1]);
        float h2 = sigf(dacc[t][2]+b.x)*tanhx(cc[t][2]);
        float h3 = sigf(dacc[t][3]+b.y)*tanhx(cc[t][3]);
        *(float2*)(g_c + n0*HH + c) = make_float2(cc[t][0], cc[t][1]);
        *(float2*)(g_c + n1*HH + c) = make_float2(cc[t][2], cc[t][3]);
        *(float2*)(g_h + n0*HH + c) = make_float2(h0, h1);
        *(float2*)(g_h + n1*HH + c) = make_float2(h2, h3);
    }
}

// ---------------------------------------------------------------------------
// Tensor level: 32 parents/block, 9 gemms, double-buffered B, 8 syncs.
// A slots: X, SUM(h0+h1), S1(h1). smem 6*8KB + 2*32KB = 114688 B -> 2 CTA/SM.
// ---------------------------------------------------------------------------
__global__ void __launch_bounds__(256, 2) tlevel_kernel(
    int sl, const float* __restrict__ x,
    const float* __restrict__ b_i, const float* __restrict__ b_f,
    const float* __restrict__ b_o, const float* __restrict__ b_u)
{
    extern __shared__ __align__(16) char sm[];
    char* Xh  = sm;
    char* Xl  = sm + ASLOT;
    char* SUh = sm + 2*ASLOT;
    char* SUl = sm + 3*ASLOT;
    char* S1h = sm + 4*ASLOT;
    char* S1l = sm + 5*ASLOT;
    char* B0  = sm + 6*ASLOT;
    char* B1  = sm + 6*ASLOT + BSLOT;

    const int tid = threadIdx.x;
    const int w = tid >> 5, l = tid & 31;
    const int mg = w >> 2, nh = w & 3;
    const int lr = l & 15, lc = l >> 4;
    const int qr = l >> 2, qc2 = (l & 3) * 2;

    const long np = (long)sl + (long)blockIdx.x * 32;
    const long cb = 2*np + 1;

    uint4 breg[8];
    ldB8(breg, 3, tid);                     // W_u
    if (tid < 192) {
        int slot = tid >> 6;                // 0=X, 1=SUM, 2=S1
        int row  = (tid & 63) >> 1;
        int half = (tid & 1) * 64;
        if (slot == 0)
            conv_row_h(Xh, Xl, row, half, x + (np + row)*HH + half, nullptr);
        else if (slot == 1)
            conv_row_h(SUh, SUl, row, half, g_h + (cb + 2*row)*HH + half,
                                            g_h + (cb + 2*row + 1)*HH + half);
        else
            conv_row_h(S1h, S1l, row, half, g_h + (cb + 2*row + 1)*HH + half, nullptr);
    }
    stB8(B0, breg, tid);
    ldB8(breg, 7, tid);                     // U_u
    __syncthreads();

    const uint32_t la = (uint32_t)((16*mg + lr)*256 + lc*16);
    const uint32_t lb = (uint32_t)(lr*256 + nh*64 + lc*16);
    const uint32_t sx = (uint32_t)(lr & 7) << 4;
    const uint32_t xH  = smem_u32(Xh),  xL  = smem_u32(Xl);
    const uint32_t suH = smem_u32(SUh), suL = smem_u32(SUl);
    const uint32_t s1H = smem_u32(S1h), s1L = smem_u32(S1l);
    const uint32_t bb0 = smem_u32(B0),  bb1 = smem_u32(B1);

    const long n0 = np + 16*mg + qr, n1 = n0 + 8;
    const int cbase = nh*32 + qc2;

    float dacc[4][4], cc[4][4], xf[4][4];

    // ---- u: X@W_u (B0) + SUM@U_u (B1) ----
    ZERO4; gemm_H(dacc, xH, xL, bb0, la, lb, sx);
    stB8(B1, breg, tid);
    ldB8(breg, 0, tid);                     // W_i
    __syncthreads();
    gemm_H(dacc, suH, suL, bb1, la, lb, sx);
    stB8(B0, breg, tid);
    ldB8(breg, 4, tid);                     // U_i
#pragma unroll
    for (int t = 0; t < 4; ++t) {
        float2 b = *(const float2*)(b_u + cbase + t*8);
        cc[t][0]=tanhx(dacc[t][0]+b.x); cc[t][1]=tanhx(dacc[t][1]+b.y);
        cc[t][2]=tanhx(dacc[t][2]+b.x); cc[t][3]=tanhx(dacc[t][3]+b.y);
    }
    __syncthreads();

    // ---- i: X@W_i (B0) + SUM@U_i (B1) ----
    ZERO4; gemm_H(dacc, xH, xL, bb0, la, lb, sx);
    stB8(B1, breg, tid);
    ldB8(breg, 1, tid);                     // W_f
    __syncthreads();
    gemm_H(dacc, suH, suL, bb1, la, lb, sx);
    stB8(B0, breg, tid);
    ldB8(breg, 5, tid);                     // U_f
#pragma unroll
    for (int t = 0; t < 4; ++t) {
        float2 b = *(const float2*)(b_i + cbase + t*8);
        cc[t][0]*=sigf(dacc[t][0]+b.x); cc[t][1]*=sigf(dacc[t][1]+b.y);
        cc[t][2]*=sigf(dacc[t][2]+b.x); cc[t][3]*=sigf(dacc[t][3]+b.y);
    }
    __syncthreads();

    // ---- f: xf = X@W_f (B0) + b_f ; G1 = S1@U_f (B1); G0 = Gsum - G1 ----
    ZERO4; gemm_H(dacc, xH, xL, bb0, la, lb, sx);
    stB8(B1, breg, tid);
    ldB8(breg, 2, tid);                     // W_o
#pragma unroll
    for (int t = 0; t < 4; ++t) {
        float2 b = *(const float2*)(b_f + cbase + t*8);
        xf[t][0]=dacc[t][0]+b.x; xf[t][1]=dacc[t][1]+b.y;
        xf[t][2]=dacc[t][2]+b.x; xf[t][3]=dacc[t][3]+b.y;
    }
    __syncthreads();
    ZERO4; gemm_H(dacc, s1H, s1L, bb1, la, lb, sx);    // G1 = h1 @ U_f
#pragma unroll
    for (int t = 0; t < 4; ++t) {                      // f1 with child1 cell
        int c = cbase + t*8;
        float2 ca = *(const float2*)(g_c + (2*n0+2)*HH + c);
        float2 cbv = *(const float2*)(g_c + (2*n1+2)*HH + c);
        cc[t][0]+=sigf(dacc[t][0]+xf[t][0])*ca.x;
        cc[t][1]+=sigf(dacc[t][1]+xf[t][1])*ca.y;
        cc[t][2]+=sigf(dacc[t][2]+xf[t][2])*cbv.x;
        cc[t][3]+=sigf(dacc[t][3]+xf[t][3])*cbv.y;
        dacc[t][0]=-dacc[t][0]; dacc[t][1]=-dacc[t][1];
        dacc[t][2]=-dacc[t][2]; dacc[t][3]=-dacc[t][3];
    }
    gemm_H(dacc, suH, suL, bb1, la, lb, sx);           // Gsum - G1 = h0 @ U_f
    stB8(B0, breg, tid);
    ldB8(breg, 6, tid);                     // U_o
#pragma unroll
    for (int t = 0; t < 4; ++t) {                      // f0 with child0 cell
        int c = cbase + t*8;
        float2 ca = *(const float2*)(g_c + (2*n0+1)*HH + c);
        float2 cbv = *(const float2*)(g_c + (2*n1+1)*HH + c);
        cc[t][0]+=sigf(dacc[t][0]+xf[t][0])*ca.x;
        cc[t][1]+=sigf(dacc[t][1]+xf[t][1])*ca.y;
        cc[t][2]+=sigf(dacc[t][2]+xf[t][2])*cbv.x;
        cc[t][3]+=sigf(dacc[t][3]+xf[t][3])*cbv.y;
    }
    __syncthreads();

    // ---- o: X@W_o (B0) + SUM@U_o (B1) + store ----
    ZERO4; gemm_H(dacc, xH, xL, bb0, la, lb, sx);
    stB8(B1, breg, tid);
    __syncthreads();
    gemm_H(dacc, suH, suL, bb1, la, lb, sx);
#pragma unroll
    for (int t = 0; t < 4; ++t) {
        int c = cbase + t*8;
        float2 b = *(const float2*)(b_o + c);
        float h0 = sigf(dacc[t][0]+b.x)*tanhx(cc[t][0]);
        float h1 = sigf(dacc[t][1]+b.y)*tanhx(cc[t][1]);
        float h2 = sigf(dacc[t][2]+b.x)*tanhx(cc[t][2]);
        float h3 = sigf(dacc[t][3]+b.y)*tanhx(cc[t][3]);
        *(float2*)(g_c + n0*HH + c) = make_float2(cc[t][0], cc[t][1]);
        *(float2*)(g_c + n1*HH + c) = make_float2(cc[t][2], cc[t][3]);
        *(float2*)(g_h + n0*HH + c) = make_float2(h0, h1);
        *(float2*)(g_h + n1*HH + c) = make_float2(h2, h3);
    }
}

// ---------------------------------------------------------------------------
// Small levels (nl <= 256): one parent/block, 512 threads, 9 k-split matvecs.
// ---------------------------------------------------------------------------
__global__ void __launch_bounds__(512) small_level_kernel(
    int sl, const float* __restrict__ x,
    const float* __restrict__ W_i, const float* __restrict__ b_i, const float* __restrict__ U_i,
    const float* __restrict__ W_f, const float* __restrict__ b_f, const float* __restrict__ U_f,
    const float* __restrict__ W_o, const float* __restrict__ b_o, const float* __restrict__ U_o,
    const float* __restrict__ W_u, const float* __restrict__ b_u, const float* __restrict__ U_u)
{
    extern __shared__ float smf[];
    float* hs   = smf;              // [h~ | h0 | h1 | x] x 128
    float* part = smf + 512;        // [9][4][128]

    const int t = threadIdx.x;
    const long node = sl + blockIdx.x;
    const long ch0  = 2*node + 1;

    if (t < 128) {
        float h0 = g_h[ch0*HH + t];
        float h1 = g_h[(ch0+1)*HH + t];
        hs[128+t] = h0; hs[256+t] = h1; hs[t] = h0 + h1;
        hs[384+t] = x[node*HH + t];
    }
    __syncthreads();

    const int col = t & 127;
    const int q   = t >> 7;
    const int kb  = q * 32;

#define JOB(J, S, M) { float av = 0.f; const float* s = hs + (S)*128;          \
        _Pragma("unroll 8")                                                    \
        for (int k = 0; k < 32; ++k) av += s[kb+k] * (M)[(kb+k)*HH + col];     \
        part[((J)*4 + q)*128 + col] = av; }
    JOB(0, 0, U_i) JOB(1, 0, U_o) JOB(2, 0, U_u)
    JOB(3, 1, U_f) JOB(4, 2, U_f)
    JOB(5, 3, W_i) JOB(6, 3, W_f) JOB(7, 3, W_o) JOB(8, 3, W_u)
#undef JOB
    __syncthreads();

    if (t < 128) {
#define SUMP(J) (part[((J)*4+0)*128+t] + part[((J)*4+1)*128+t] + \
                 part[((J)*4+2)*128+t] + part[((J)*4+3)*128+t])
        float yi  = SUMP(0), yo = SUMP(1), yu = SUMP(2);
        float yf0 = SUMP(3), yf1 = SUMP(4);
        float xi  = SUMP(5) + b_i[t];
        float xfv = SUMP(6) + b_f[t];
        float xo  = SUMP(7) + b_o[t];
        float xu  = SUMP(8) + b_u[t];
#undef SUMP
        float c = sigf(xi+yi)*tanhx(xu+yu)
                + sigf(xfv+yf0)*g_c[ch0*HH+t] + sigf(xfv+yf1)*g_c[(ch0+1)*HH+t];
        g_c[node*HH+t] = c;
        g_h[node*HH+t] = sigf(xo+yo)*tanhx(c);
    }
}

__global__ void out_kernel(float* __restrict__ out)
{
    int t = threadIdx.x;
    out[t] = (t < 128) ? g_h[t] : g_c[t - 128];
}

// ---------------------------------------------------------------------------
extern "C" void kernel_launch(void* const* d_in, const int* in_sizes, int n_in,
                              void* d_out, int out_size)
{
    const float* x   = (const float*)d_in[0];
    const float* W_i = (const float*)d_in[1];
    const float* b_i = (const float*)d_in[2];
    const float* U_i = (const float*)d_in[3];
    const float* W_f = (const float*)d_in[4];
    const float* b_f = (const float*)d_in[5];
    const float* U_f = (const float*)d_in[6];
    const float* W_o = (const float*)d_in[7];
    const float* b_o = (const float*)d_in[8];
    const float* U_o = (const float*)d_in[9];
    const float* W_u = (const float*)d_in[10];
    const float* b_u = (const float*)d_in[11];
    const float* U_u = (const float*)d_in[12];

    const int SMEM_T = 6*ASLOT + 2*BSLOT;    // 114688
    const int SMEM_L = 2*ASLOT + 2*BSLOT;    // 81920
    const int SMEM_S = (512 + 9*4*128) * 4;
    cudaFuncSetAttribute(tlevel_kernel, cudaFuncAttributeMaxDynamicSharedMemorySize, SMEM_T);
    cudaFuncSetAttribute(leaf_kernel,   cudaFuncAttributeMaxDynamicSharedMemorySize, SMEM_L);
    cudaFuncSetAttribute(small_level_kernel, cudaFuncAttributeMaxDynamicSharedMemorySize, SMEM_S);

    conv_w_kernel<<<8, 256>>>(W_i, W_f, W_o, W_u, U_i, U_f, U_o, U_u);

    leaf_kernel<<<131072 / 32, 256, SMEM_L>>>(x, b_i, b_o, b_u);

    for (int l = DEPTH - 1; l >= 0; --l) {
        int nl = 1 << l;
        int sl = nl - 1;
        if (nl >= 512)
            tlevel_kernel<<<nl / 32, 256, SMEM_T>>>(sl, x, b_i, b_f, b_o, b_u);
        else
            small_level_kernel<<<nl, 512, SMEM_S>>>(sl, x,
                W_i, b_i, U_i, W_f, b_f, U_f, W_o, b_o, U_o, W_u, b_u, U_u);
    }

    out_kernel<<<1, 256>>>((float*)d_out);
}

// round 15
// speedup vs baseline: 1.1728x; 1.0855x over previous
#include <cuda_runtime.h>
#include <cuda_fp16.h>
#include <cstdint>

// ---------------------------------------------------------------------------
// ChildSumTreeLSTM depth 17, D=H=128. R15: R14 with the tlevel64 B-loader
// fixed (half tile = 1024 uint4, row stride 16 uint4, c0u = half*8).
// fp16 2-pass HMMA, 32 parents/block, 2 CTAs/SM; small cutoff nl<=256;
// column-split N=64 tlevel for underfilled levels 9-12.
// ---------------------------------------------------------------------------

#define DEPTH   17
#define HH      128
#define NNODES  ((1 << (DEPTH + 1)) - 1)
#define PITCH   136
#define BPITCH  72

__device__ float g_h[33554304L];
__device__ float g_c[33554304L];
// fp16 weight images, dense [k][n]. mats: 0..3 = W_i,W_f,W_o,W_u ; 4..7 = U_*
__device__ uint4 g_Wh[8][2048];

__device__ __forceinline__ float sigf(float v)  { return 1.0f / (1.0f + __expf(-v)); }
__device__ __forceinline__ float tanhx(float v) {
    float r; asm("tanh.approx.f32 %0, %1;" : "=f"(r) : "f"(v)); return r;
}
__device__ __forceinline__ uint32_t smem_u32(const void* p) {
    uint32_t a; asm("{ .reg .u64 t; cvta.to.shared.u64 t, %1; cvt.u32.u64 %0, t; }"
                    : "=r"(a) : "l"(p)); return a;
}
__device__ __forceinline__ void ldsm4(uint32_t& r0, uint32_t& r1, uint32_t& r2,
                                      uint32_t& r3, uint32_t a) {
    asm volatile("ldmatrix.sync.aligned.m8n8.x4.shared.b16 {%0,%1,%2,%3}, [%4];"
                 : "=r"(r0), "=r"(r1), "=r"(r2), "=r"(r3) : "r"(a));
}
__device__ __forceinline__ void ldsm4t(uint32_t& r0, uint32_t& r1, uint32_t& r2,
                                       uint32_t& r3, uint32_t a) {
    asm volatile("ldmatrix.sync.aligned.m8n8.x4.trans.shared.b16 {%0,%1,%2,%3}, [%4];"
                 : "=r"(r0), "=r"(r1), "=r"(r2), "=r"(r3) : "r"(a));
}
__device__ __forceinline__ void mmaH(float* c, uint32_t a0, uint32_t a1,
                                     uint32_t a2, uint32_t a3,
                                     uint32_t b0, uint32_t b1) {
    asm volatile("mma.sync.aligned.m16n8k16.row.col.f32.f16.f16.f32 "
                 "{%0,%1,%2,%3}, {%4,%5,%6,%7}, {%8,%9}, {%0,%1,%2,%3};"
                 : "+f"(c[0]), "+f"(c[1]), "+f"(c[2]), "+f"(c[3])
                 : "r"(a0), "r"(a1), "r"(a2), "r"(a3), "r"(b0), "r"(b1));
}
__device__ __forceinline__ void split2h(float a, float b, uint32_t& hi, uint32_t& lo) {
    __half2 h = __floats2half2_rn(a, b);
    float ra = a - __low2float(h);
    float rb = b - __high2float(h);
    __half2 l = __floats2half2_rn(ra, rb);
    hi = *(uint32_t*)&h; lo = *(uint32_t*)&l;
}

// fp16 2-pass GEMM: dacc[4][4] += (A_hi + A_lo) @ B. Warp: 16 rows x 32 cols.
__device__ __forceinline__ void gemm_H(float (*dacc)[4], uint32_t aH, uint32_t aL,
                                       uint32_t bB, int bstep)
{
#pragma unroll
    for (int kc = 0; kc < 8; ++kc) {
        uint32_t ah0,ah1,ah2,ah3, al0,al1,al2,al3;
        ldsm4(ah0,ah1,ah2,ah3, aH + kc*32);
        ldsm4(al0,al1,al2,al3, aL + kc*32);
        uint32_t bp = bB + kc*bstep;
        uint32_t b0,b1,b2,b3, b4,b5,b6,b7;
        ldsm4t(b0,b1,b2,b3, bp);
        ldsm4t(b4,b5,b6,b7, bp + 32);
        mmaH(dacc[0], ah0,ah1,ah2,ah3, b0,b1);
        mmaH(dacc[1], ah0,ah1,ah2,ah3, b2,b3);
        mmaH(dacc[2], ah0,ah1,ah2,ah3, b4,b5);
        mmaH(dacc[3], ah0,ah1,ah2,ah3, b6,b7);
        mmaH(dacc[0], al0,al1,al2,al3, b0,b1);
        mmaH(dacc[1], al0,al1,al2,al3, b2,b3);
        mmaH(dacc[2], al0,al1,al2,al3, b4,b5);
        mmaH(dacc[3], al0,al1,al2,al3, b6,b7);
    }
}

// B staging, 256-thread kernels: full 128x128 tile, 8 uint4/thread
__device__ __forceinline__ void ldB8(uint4* r, int mat, int tid) {
    const uint4* src = g_Wh[mat];
#pragma unroll
    for (int q = 0; q < 8; ++q) r[q] = src[tid + q*256];
}
__device__ __forceinline__ void stB8(__half* Bp, const uint4* r, int tid) {
#pragma unroll
    for (int q = 0; q < 8; ++q) {
        int i = tid + q*256, row = i >> 4, ch = i & 15;
        *(uint4*)(Bp + row*PITCH + ch*8) = r[q];
    }
}
// B staging, 128-thread kernels: half tile (128 rows x 64 cols = 1024 uint4).
// Each weight row = 16 uint4; c0u = column-half offset in uint4 (0 or 8).
__device__ __forceinline__ void ldB4(uint4* r, int mat, int c0u, int tid) {
    const uint4* src = g_Wh[mat];
#pragma unroll
    for (int q = 0; q < 8; ++q) {
        int i = tid + q*128, row = i >> 3, ch = i & 7;
        r[q] = src[row*16 + c0u + ch];
    }
}
__device__ __forceinline__ void stB4(__half* Bp, const uint4* r, int tid) {
#pragma unroll
    for (int q = 0; q < 8; ++q) {
        int i = tid + q*128, row = i >> 3, ch = i & 7;
        *(uint4*)(Bp + row*BPITCH + ch*8) = r[q];
    }
}

__global__ void conv_w_kernel(
    const float* __restrict__ W_i, const float* __restrict__ W_f,
    const float* __restrict__ W_o, const float* __restrict__ W_u,
    const float* __restrict__ U_i, const float* __restrict__ U_f,
    const float* __restrict__ U_o, const float* __restrict__ U_u)
{
    const float* mats[8] = { W_i, W_f, W_o, W_u, U_i, U_f, U_o, U_u };
    const float* M = mats[blockIdx.x];
    __half* dst = (__half*)&g_Wh[blockIdx.x][0];
    for (int idx = threadIdx.x; idx < 16384; idx += blockDim.x)
        dst[idx] = __float2half(M[idx]);
}

__device__ __forceinline__ void conv_row_h(__half* dh, __half* dl,
                                           int row, int half,
                                           const float* __restrict__ s0,
                                           const float* __restrict__ s1)
{
#pragma unroll
    for (int i = 0; i < 16; ++i) {
        float4 v = *(const float4*)(s0 + i*4);
        if (s1) {
            float4 w = *(const float4*)(s1 + i*4);
            v.x += w.x; v.y += w.y; v.z += w.z; v.w += w.w;
        }
        uint32_t h0,l0,h1,l1;
        split2h(v.x,v.y,h0,l0); split2h(v.z,v.w,h1,l1);
        *(uint2*)(dh + row*PITCH + half + i*4) = make_uint2(h0,h1);
        *(uint2*)(dl + row*PITCH + half + i*4) = make_uint2(l0,l1);
    }
}

#define ZERO4 { _Pragma("unroll") for (int t = 0; t < 4; ++t) \
        { dacc[t][0]=0.f; dacc[t][1]=0.f; dacc[t][2]=0.f; dacc[t][3]=0.f; } }

// ---------------------------------------------------------------------------
// Leaf: 32 leaves/block, 256 threads, 2 CTAs/SM. Gates u,i,o from x@W.
// ---------------------------------------------------------------------------
__global__ void __launch_bounds__(256, 2) leaf_kernel(
    const float* __restrict__ x,
    const float* __restrict__ b_i, const float* __restrict__ b_o,
    const float* __restrict__ b_u)
{
    extern __shared__ __align__(16) __half sm[];
    __half* Xh = sm;
    __half* Xl = sm + 32*PITCH;
    __half* Bp = sm + 64*PITCH;

    const int tid = threadIdx.x;
    const int w = tid >> 5, l = tid & 31;
    const int mg = w >> 2, nh = w & 3;
    const int lr = l & 15, lc = l >> 4;
    const int qr = l >> 2, qc2 = (l & 3) * 2;
    const long np = 131071L + (long)blockIdx.x * 32;

    uint4 breg[8];
    ldB8(breg, 3, tid);                     // W_u
    if (tid < 64) {
        int row = tid >> 1, half = (tid & 1) * 64;
        conv_row_h(Xh, Xl, row, half, x + (np + row)*HH + half, nullptr);
    }
    stB8(Bp, breg, tid);
    __syncthreads();

    const uint32_t a_off = (uint32_t)((16*mg + lr)*PITCH + lc*8)*2;
    const uint32_t b_off = (uint32_t)(lr*PITCH + nh*32 + lc*8)*2;
    const uint32_t xH = smem_u32(Xh)+a_off, xL = smem_u32(Xl)+a_off;
    const uint32_t bB = smem_u32(Bp)+b_off;

    const long n0 = np + 16*mg + qr, n1 = n0 + 8;
    const int cbase = nh*32 + qc2;

    float dacc[4][4], cc[4][4];
#define SWAPB() do { __syncthreads(); stB8(Bp, breg, tid); __syncthreads(); } while (0)

    ldB8(breg, 0, tid);                     // W_i prefetch
    ZERO4; gemm_H(dacc, xH, xL, bB, 16*PITCH*2);
#pragma unroll
    for (int t = 0; t < 4; ++t) {
        float2 b = *(const float2*)(b_u + cbase + t*8);
        cc[t][0]=tanhx(dacc[t][0]+b.x); cc[t][1]=tanhx(dacc[t][1]+b.y);
        cc[t][2]=tanhx(dacc[t][2]+b.x); cc[t][3]=tanhx(dacc[t][3]+b.y);
    }
    SWAPB();                                // B = W_i
    ldB8(breg, 2, tid);                     // W_o prefetch
    ZERO4; gemm_H(dacc, xH, xL, bB, 16*PITCH*2);
#pragma unroll
    for (int t = 0; t < 4; ++t) {
        float2 b = *(const float2*)(b_i + cbase + t*8);
        cc[t][0]*=sigf(dacc[t][0]+b.x); cc[t][1]*=sigf(dacc[t][1]+b.y);
        cc[t][2]*=sigf(dacc[t][2]+b.x); cc[t][3]*=sigf(dacc[t][3]+b.y);
    }
    SWAPB();                                // B = W_o
    ZERO4; gemm_H(dacc, xH, xL, bB, 16*PITCH*2);
#pragma unroll
    for (int t = 0; t < 4; ++t) {
        int c = cbase + t*8;
        float2 b = *(const float2*)(b_o + c);
        float h0 = sigf(dacc[t][0]+b.x)*tanhx(cc[t][0]);
        float h1 = sigf(dacc[t][1]+b.y)*tanhx(cc[t][1]);
        float h2 = sigf(dacc[t][2]+b.x)*tanhx(cc[t][2]);
        float h3 = sigf(dacc[t][3]+b.y)*tanhx(cc[t][3]);
        *(float2*)(g_c + n0*HH + c) = make_float2(cc[t][0], cc[t][1]);
        *(float2*)(g_c + n1*HH + c) = make_float2(cc[t][2], cc[t][3]);
        *(float2*)(g_h + n0*HH + c) = make_float2(h0, h1);
        *(float2*)(g_h + n1*HH + c) = make_float2(h2, h3);
    }
#undef SWAPB
}

// ---------------------------------------------------------------------------
// Tensor level (full N=128): 32 parents/block, 256 threads, 2 CTAs/SM.
// ---------------------------------------------------------------------------
__global__ void __launch_bounds__(256, 2) tlevel_kernel(
    int sl, const float* __restrict__ x,
    const float* __restrict__ b_i, const float* __restrict__ b_f,
    const float* __restrict__ b_o, const float* __restrict__ b_u)
{
    constexpr int AS = 32 * PITCH;
    extern __shared__ __align__(16) __half sm[];
    __half* Xh  = sm;
    __half* Xl  = sm + AS;
    __half* SUh = sm + 2*AS;
    __half* SUl = sm + 3*AS;
    __half* S1h = sm + 4*AS;
    __half* S1l = sm + 5*AS;
    __half* Bp  = sm + 6*AS;

    const int tid = threadIdx.x;
    const int w = tid >> 5, l = tid & 31;
    const int mg = w >> 2, nh = w & 3;
    const int lr = l & 15, lc = l >> 4;
    const int qr = l >> 2, qc2 = (l & 3) * 2;

    const long np = (long)sl + (long)blockIdx.x * 32;
    const long cb = 2*np + 1;

    uint4 breg[8];
    ldB8(breg, 3, tid);                     // W_u
    if (tid < 192) {
        int slot = tid >> 6;                // 0=X, 1=SUM, 2=S1
        int row  = (tid & 63) >> 1;
        int half = (tid & 1) * 64;
        if (slot == 0)
            conv_row_h(Xh, Xl, row, half, x + (np + row)*HH + half, nullptr);
        else if (slot == 1)
            conv_row_h(SUh, SUl, row, half, g_h + (cb + 2*row)*HH + half,
                                            g_h + (cb + 2*row + 1)*HH + half);
        else
            conv_row_h(S1h, S1l, row, half, g_h + (cb + 2*row + 1)*HH + half, nullptr);
    }
    stB8(Bp, breg, tid);
    __syncthreads();

    const uint32_t a_off = (uint32_t)((16*mg + lr)*PITCH + lc*8)*2;
    const uint32_t b_off = (uint32_t)(lr*PITCH + nh*32 + lc*8)*2;
    const uint32_t xH  = smem_u32(Xh)+a_off,  xL  = smem_u32(Xl)+a_off;
    const uint32_t suH = smem_u32(SUh)+a_off, suL = smem_u32(SUl)+a_off;
    const uint32_t s1H = smem_u32(S1h)+a_off, s1L = smem_u32(S1l)+a_off;
    const uint32_t bB  = smem_u32(Bp)+b_off;

    const long n0 = np + 16*mg + qr, n1 = n0 + 8;
    const int cbase = nh*32 + qc2;

    float dacc[4][4], cc[4][4], xf[4][4];
#define SWAPB() do { __syncthreads(); stB8(Bp, breg, tid); __syncthreads(); } while (0)
#define BSTEP (16*PITCH*2)

    // ---- u ----
    ldB8(breg, 7, tid);                     // U_u
    ZERO4; gemm_H(dacc, xH, xL, bB, BSTEP);
    SWAPB();                                // B = U_u
    ldB8(breg, 0, tid);                     // W_i
    gemm_H(dacc, suH, suL, bB, BSTEP);
#pragma unroll
    for (int t = 0; t < 4; ++t) {
        float2 b = *(const float2*)(b_u + cbase + t*8);
        cc[t][0]=tanhx(dacc[t][0]+b.x); cc[t][1]=tanhx(dacc[t][1]+b.y);
        cc[t][2]=tanhx(dacc[t][2]+b.x); cc[t][3]=tanhx(dacc[t][3]+b.y);
    }
    // ---- i ----
    SWAPB();                                // B = W_i
    ldB8(breg, 4, tid);                     // U_i
    ZERO4; gemm_H(dacc, xH, xL, bB, BSTEP);
    SWAPB();                                // B = U_i
    ldB8(breg, 1, tid);                     // W_f
    gemm_H(dacc, suH, suL, bB, BSTEP);
#pragma unroll
    for (int t = 0; t < 4; ++t) {
        float2 b = *(const float2*)(b_i + cbase + t*8);
        cc[t][0]*=sigf(dacc[t][0]+b.x); cc[t][1]*=sigf(dacc[t][1]+b.y);
        cc[t][2]*=sigf(dacc[t][2]+b.x); cc[t][3]*=sigf(dacc[t][3]+b.y);
    }
    // ---- f ----
    SWAPB();                                // B = W_f
    ldB8(breg, 5, tid);                     // U_f
    ZERO4; gemm_H(dacc, xH, xL, bB, BSTEP);
#pragma unroll
    for (int t = 0; t < 4; ++t) {
        float2 b = *(const float2*)(b_f + cbase + t*8);
        xf[t][0]=dacc[t][0]+b.x; xf[t][1]=dacc[t][1]+b.y;
        xf[t][2]=dacc[t][2]+b.x; xf[t][3]=dacc[t][3]+b.y;
    }
    SWAPB();                                // B = U_f
    ldB8(breg, 2, tid);                     // W_o
    ZERO4; gemm_H(dacc, s1H, s1L, bB, BSTEP);          // G1 = h1 @ U_f
#pragma unroll
    for (int t = 0; t < 4; ++t) {                      // f1 with child1 cell
        int c = cbase + t*8;
        float2 ca = *(const float2*)(g_c + (2*n0+2)*HH + c);
        float2 cbv = *(const float2*)(g_c + (2*n1+2)*HH + c);
        cc[t][0]+=sigf(dacc[t][0]+xf[t][0])*ca.x;
        cc[t][1]+=sigf(dacc[t][1]+xf[t][1])*ca.y;
        cc[t][2]+=sigf(dacc[t][2]+xf[t][2])*cbv.x;
        cc[t][3]+=sigf(dacc[t][3]+xf[t][3])*cbv.y;
        dacc[t][0]=-dacc[t][0]; dacc[t][1]=-dacc[t][1];
        dacc[t][2]=-dacc[t][2]; dacc[t][3]=-dacc[t][3];
    }
    gemm_H(dacc, suH, suL, bB, BSTEP);                 // Gsum - G1 = h0 @ U_f
#pragma unroll
    for (int t = 0; t < 4; ++t) {                      // f0 with child0 cell
        int c = cbase + t*8;
        float2 ca = *(const float2*)(g_c + (2*n0+1)*HH + c);
        float2 cbv = *(const float2*)(g_c + (2*n1+1)*HH + c);
        cc[t][0]+=sigf(dacc[t][0]+xf[t][0])*ca.x;
        cc[t][1]+=sigf(dacc[t][1]+xf[t][1])*ca.y;
        cc[t][2]+=sigf(dacc[t][2]+xf[t][2])*cbv.x;
        cc[t][3]+=sigf(dacc[t][3]+xf[t][3])*cbv.y;
    }
    // ---- o + store ----
    SWAPB();                                // B = W_o
    ldB8(breg, 6, tid);                     // U_o
    ZERO4; gemm_H(dacc, xH, xL, bB, BSTEP);
    SWAPB();                                // B = U_o
    gemm_H(dacc, suH, suL, bB, BSTEP);
#pragma unroll
    for (int t = 0; t < 4; ++t) {
        int c = cbase + t*8;
        float2 b = *(const float2*)(b_o + c);
        float h0 = sigf(dacc[t][0]+b.x)*tanhx(cc[t][0]);
        float h1 = sigf(dacc[t][1]+b.y)*tanhx(cc[t][1]);
        float h2 = sigf(dacc[t][2]+b.x)*tanhx(cc[t][2]);
        float h3 = sigf(dacc[t][3]+b.y)*tanhx(cc[t][3]);
        *(float2*)(g_c + n0*HH + c) = make_float2(cc[t][0], cc[t][1]);
        *(float2*)(g_c + n1*HH + c) = make_float2(cc[t][2], cc[t][3]);
        *(float2*)(g_h + n0*HH + c) = make_float2(h0, h1);
        *(float2*)(g_h + n1*HH + c) = make_float2(h2, h3);
    }
#undef SWAPB
#undef BSTEP
}

// ---------------------------------------------------------------------------
// Column-split tensor level (N=64): 32 parents/block, 128 threads, 3 CTAs/SM.
// bid>>1 selects parents, bid&1 selects column half.
// ---------------------------------------------------------------------------
__global__ void __launch_bounds__(128, 3) tlevel64_kernel(
    int sl, const float* __restrict__ x,
    const float* __restrict__ b_i, const float* __restrict__ b_f,
    const float* __restrict__ b_o, const float* __restrict__ b_u)
{
    constexpr int AS = 32 * PITCH;
    extern __shared__ __align__(16) __half sm[];
    __half* Xh  = sm;
    __half* Xl  = sm + AS;
    __half* SUh = sm + 2*AS;
    __half* SUl = sm + 3*AS;
    __half* S1h = sm + 4*AS;
    __half* S1l = sm + 5*AS;
    __half* Bp  = sm + 6*AS;

    const int tid = threadIdx.x;
    const int w = tid >> 5, l = tid & 31;
    const int mg = w >> 1, nh = w & 1;
    const int lr = l & 15, lc = l >> 4;
    const int qr = l >> 2, qc2 = (l & 3) * 2;

    const int  c0  = (blockIdx.x & 1) * 64;      // column half
    const int  c0u = (blockIdx.x & 1) * 8;       // uint4 offset in weight rows
    const long np  = (long)sl + (long)(blockIdx.x >> 1) * 32;
    const long cb  = 2*np + 1;

    uint4 breg[8];
    ldB4(breg, 3, c0u, tid);                // W_u half
    for (int j = tid; j < 192; j += 128) {
        int slot = j >> 6;
        int row  = (j & 63) >> 1;
        int half = (j & 1) * 64;
        if (slot == 0)
            conv_row_h(Xh, Xl, row, half, x + (np + row)*HH + half, nullptr);
        else if (slot == 1)
            conv_row_h(SUh, SUl, row, half, g_h + (cb + 2*row)*HH + half,
                                            g_h + (cb + 2*row + 1)*HH + half);
        else
            conv_row_h(S1h, S1l, row, half, g_h + (cb + 2*row + 1)*HH + half, nullptr);
    }
    stB4(Bp, breg, tid);
    __syncthreads();

    const uint32_t a_off = (uint32_t)((16*mg + lr)*PITCH + lc*8)*2;
    const uint32_t b_off = (uint32_t)(lr*BPITCH + nh*32 + lc*8)*2;
    const uint32_t xH  = smem_u32(Xh)+a_off,  xL  = smem_u32(Xl)+a_off;
    const uint32_t suH = smem_u32(SUh)+a_off, suL = smem_u32(SUl)+a_off;
    const uint32_t s1H = smem_u32(S1h)+a_off, s1L = smem_u32(S1l)+a_off;
    const uint32_t bB  = smem_u32(Bp)+b_off;

    const long n0 = np + 16*mg + qr, n1 = n0 + 8;
    const int cbase = c0 + nh*32 + qc2;

    float dacc[4][4], cc[4][4], xf[4][4];
#define SWAPB() do { __syncthreads(); stB4(Bp, breg, tid); __syncthreads(); } while (0)
#define BSTEP (16*BPITCH*2)

    // ---- u ----
    ldB4(breg, 7, c0u, tid);                // U_u
    ZERO4; gemm_H(dacc, xH, xL, bB, BSTEP);
    SWAPB();
    ldB4(breg, 0, c0u, tid);                // W_i
    gemm_H(dacc, suH, suL, bB, BSTEP);
#pragma unroll
    for (int t = 0; t < 4; ++t) {
        float2 b = *(const float2*)(b_u + cbase + t*8);
        cc[t][0]=tanhx(dacc[t][0]+b.x); cc[t][1]=tanhx(dacc[t][1]+b.y);
        cc[t][2]=tanhx(dacc[t][2]+b.x); cc[t][3]=tanhx(dacc[t][3]+b.y);
    }
    // ---- i ----
    SWAPB();
    ldB4(breg, 4, c0u, tid);                // U_i
    ZERO4; gemm_H(dacc, xH, xL, bB, BSTEP);
    SWAPB();
    ldB4(breg, 1, c0u, tid);                // W_f
    gemm_H(dacc, suH, suL, bB, BSTEP);
#pragma unroll
    for (int t = 0; t < 4; ++t) {
        float2 b = *(const float2*)(b_i + cbase + t*8);
        cc[t][0]*=sigf(dacc[t][0]+b.x); cc[t][1]*=sigf(dacc[t][1]+b.y);
        cc[t][2]*=sigf(dacc[t][2]+b.x); cc[t][3]*=sigf(dacc[t][3]+b.y);
    }
    // ---- f ----
    SWAPB();
    ldB4(breg, 5, c0u, tid);                // U_f
    ZERO4; gemm_H(dacc, xH, xL, bB, BSTEP);
#pragma unroll
    for (int t = 0; t < 4; ++t) {
        float2 b = *(const float2*)(b_f + cbase + t*8);
        xf[t][0]=dacc[t][0]+b.x; xf[t][1]=dacc[t][1]+b.y;
        xf[t][2]=dacc[t][2]+b.x; xf[t][3]=dacc[t][3]+b.y;
    }
    SWAPB();
    ldB4(breg, 2, c0u, tid);                // W_o
    ZERO4; gemm_H(dacc, s1H, s1L, bB, BSTEP);          // G1 = h1 @ U_f
#pragma unroll
    for (int t = 0; t < 4; ++t) {
        int c = cbase + t*8;
        float2 ca = *(const float2*)(g_c + (2*n0+2)*HH + c);
        float2 cbv = *(const float2*)(g_c + (2*n1+2)*HH + c);
        cc[t][0]+=sigf(dacc[t][0]+xf[t][0])*ca.x;
        cc[t][1]+=sigf(dacc[t][1]+xf[t][1])*ca.y;
        cc[t][2]+=sigf(dacc[t][2]+xf[t][2])*cbv.x;
        cc[t][3]+=sigf(dacc[t][3]+xf[t][3])*cbv.y;
        dacc[t][0]=-dacc[t][0]; dacc[t][1]=-dacc[t][1];
        dacc[t][2]=-dacc[t][2]; dacc[t][3]=-dacc[t][3];
    }
    gemm_H(dacc, suH, suL, bB, BSTEP);                 // Gsum - G1 = h0 @ U_f
#pragma unroll
    for (int t = 0; t < 4; ++t) {
        int c = cbase + t*8;
        float2 ca = *(const float2*)(g_c + (2*n0+1)*HH + c);
        float2 cbv = *(const float2*)(g_c + (2*n1+1)*HH + c);
        cc[t][0]+=sigf(dacc[t][0]+xf[t][0])*ca.x;
        cc[t][1]+=sigf(dacc[t][1]+xf[t][1])*ca.y;
        cc[t][2]+=sigf(dacc[t][2]+xf[t][2])*cbv.x;
        cc[t][3]+=sigf(dacc[t][3]+xf[t][3])*cbv.y;
    }
    // ---- o + store ----
    SWAPB();
    ldB4(breg, 6, c0u, tid);                // U_o
    ZERO4; gemm_H(dacc, xH, xL, bB, BSTEP);
    SWAPB();
    gemm_H(dacc, suH, suL, bB, BSTEP);
#pragma unroll
    for (int t = 0; t < 4; ++t) {
        int c = cbase + t*8;
        float2 b = *(const float2*)(b_o + c);
        float h0 = sigf(dacc[t][0]+b.x)*tanhx(cc[t][0]);
        float h1 = sigf(dacc[t][1]+b.y)*tanhx(cc[t][1]);
        float h2 = sigf(dacc[t][2]+b.x)*tanhx(cc[t][2]);
        float h3 = sigf(dacc[t][3]+b.y)*tanhx(cc[t][3]);
        *(float2*)(g_c + n0*HH + c) = make_float2(cc[t][0], cc[t][1]);
        *(float2*)(g_c + n1*HH + c) = make_float2(cc[t][2], cc[t][3]);
        *(float2*)(g_h + n0*HH + c) = make_float2(h0, h1);
        *(float2*)(g_h + n1*HH + c) = make_float2(h2, h3);
    }
#undef SWAPB
#undef BSTEP
}

// ---------------------------------------------------------------------------
// Small levels (nl <= 256): one parent/block, 512 threads, 9 k-split matvecs.
// ---------------------------------------------------------------------------
__global__ void __launch_bounds__(512) small_level_kernel(
    int sl, const float* __restrict__ x,
    const float* __restrict__ W_i, const float* __restrict__ b_i, const float* __restrict__ U_i,
    const float* __restrict__ W_f, const float* __restrict__ b_f, const float* __restrict__ U_f,
    const float* __restrict__ W_o, const float* __restrict__ b_o, const float* __restrict__ U_o,
    const float* __restrict__ W_u, const float* __restrict__ b_u, const float* __restrict__ U_u)
{
    extern __shared__ float smf[];
    float* hs   = smf;              // [h~ | h0 | h1 | x] x 128
    float* part = smf + 512;        // [9][4][128]

    const int t = threadIdx.x;
    const long node = sl + blockIdx.x;
    const long ch0  = 2*node + 1;

    if (t < 128) {
        float h0 = g_h[ch0*HH + t];
        float h1 = g_h[(ch0+1)*HH + t];
        hs[128+t] = h0; hs[256+t] = h1; hs[t] = h0 + h1;
        hs[384+t] = x[node*HH + t];
    }
    __syncthreads();

    const int col = t & 127;
    const int q   = t >> 7;
    const int kb  = q * 32;

#define JOB(J, S, M) { float av = 0.f; const float* s = hs + (S)*128;          \
        _Pragma("unroll 8")                                                    \
        for (int k = 0; k < 32; ++k) av += s[kb+k] * (M)[(kb+k)*HH + col];     \
        part[((J)*4 + q)*128 + col] = av; }
    JOB(0, 0, U_i) JOB(1, 0, U_o) JOB(2, 0, U_u)
    JOB(3, 1, U_f) JOB(4, 2, U_f)
    JOB(5, 3, W_i) JOB(6, 3, W_f) JOB(7, 3, W_o) JOB(8, 3, W_u)
#undef JOB
    __syncthreads();

    if (t < 128) {
#define SUMP(J) (part[((J)*4+0)*128+t] + part[((J)*4+1)*128+t] + \
                 part[((J)*4+2)*128+t] + part[((J)*4+3)*128+t])
        float yi  = SUMP(0), yo = SUMP(1), yu = SUMP(2);
        float yf0 = SUMP(3), yf1 = SUMP(4);
        float xi  = SUMP(5) + b_i[t];
        float xfv = SUMP(6) + b_f[t];
        float xo  = SUMP(7) + b_o[t];
        float xu  = SUMP(8) + b_u[t];
#undef SUMP
        float c = sigf(xi+yi)*tanhx(xu+yu)
                + sigf(xfv+yf0)*g_c[ch0*HH+t] + sigf(xfv+yf1)*g_c[(ch0+1)*HH+t];
        g_c[node*HH+t] = c;
        g_h[node*HH+t] = sigf(xo+yo)*tanhx(c);
    }
}

__global__ void out_kernel(float* __restrict__ out)
{
    int t = threadIdx.x;
    out[t] = (t < 128) ? g_h[t] : g_c[t - 128];
}

// ---------------------------------------------------------------------------
extern "C" void kernel_launch(void* const* d_in, const int* in_sizes, int n_in,
                              void* d_out, int out_size)
{
    const float* x   = (const float*)d_in[0];
    const float* W_i = (const float*)d_in[1];
    const float* b_i = (const float*)d_in[2];
    const float* U_i = (const float*)d_in[3];
    const float* W_f = (const float*)d_in[4];
    const float* b_f = (const float*)d_in[5];
    const float* U_f = (const float*)d_in[6];
    const float* W_o = (const float*)d_in[7];
    const float* b_o = (const float*)d_in[8];
    const float* U_o = (const float*)d_in[9];
    const float* W_u = (const float*)d_in[10];
    const float* b_u = (const float*)d_in[11];
    const float* U_u = (const float*)d_in[12];

    const int SMEM_T   = (6*32*PITCH + 128*PITCH) * 2;   // 87040
    const int SMEM_T64 = 6*32*PITCH*2 + 128*BPITCH*2;    // 70656
    const int SMEM_L   = (2*32*PITCH + 128*PITCH) * 2;   // 52224
    const int SMEM_S   = (512 + 9*4*128) * 4;
    cudaFuncSetAttribute(tlevel_kernel,   cudaFuncAttributeMaxDynamicSharedMemorySize, SMEM_T);
    cudaFuncSetAttribute(tlevel64_kernel, cudaFuncAttributeMaxDynamicSharedMemorySize, SMEM_T64);
    cudaFuncSetAttribute(leaf_kernel,     cudaFuncAttributeMaxDynamicSharedMemorySize, SMEM_L);
    cudaFuncSetAttribute(small_level_kernel, cudaFuncAttributeMaxDynamicSharedMemorySize, SMEM_S);

    conv_w_kernel<<<8, 256>>>(W_i, W_f, W_o, W_u, U_i, U_f, U_o, U_u);

    leaf_kernel<<<131072 / 32, 256, SMEM_L>>>(x, b_i, b_o, b_u);

    for (int l = DEPTH - 1; l >= 0; --l) {
        int nl = 1 << l;
        int sl = nl - 1;
        if (nl >= 8192)
            tlevel_kernel<<<nl / 32, 256, SMEM_T>>>(sl, x, b_i, b_f, b_o, b_u);
        else if (nl >= 512)
            tlevel64_kernel<<<(nl / 32) * 2, 128, SMEM_T64>>>(sl, x, b_i, b_f, b_o, b_u);
        else
            small_level_kernel<<<nl, 512, SMEM_S>>>(sl, x,
                W_i, b_i, U_i, W_f, b_f, U_f, W_o, b_o, U_o, W_u, b_u, U_u);
    }

    out_kernel<<<1, 256>>>((float*)d_out);
}

// round 16
// speedup vs baseline: 1.2597x; 1.0741x over previous
#include <cuda_runtime.h>
#include <cuda_fp16.h>
#include <cstdint>

// ---------------------------------------------------------------------------
// ChildSumTreeLSTM depth 17, D=H=128. R16: single-pass fp16 HMMA (A and B
// both fp16; error ~2-4e-4, threshold 1e-3). Halves MMA+LDSM per gemm and
// all A smem. 32 parents/block, 2 CTAs/SM; N=64 split levels 9-13 (4 CTA/SM);
// small kernel nl<=256.
// ---------------------------------------------------------------------------

#define DEPTH   17
#define HH      128
#define NNODES  ((1 << (DEPTH + 1)) - 1)
#define PITCH   136
#define BPITCH  72

__device__ float g_h[33554304L];
__device__ float g_c[33554304L];
// fp16 weight images, dense [k][n]. mats: 0..3 = W_i,W_f,W_o,W_u ; 4..7 = U_*
__device__ uint4 g_Wh[8][2048];

__device__ __forceinline__ float sigf(float v)  { return 1.0f / (1.0f + __expf(-v)); }
__device__ __forceinline__ float tanhx(float v) {
    float r; asm("tanh.approx.f32 %0, %1;" : "=f"(r) : "f"(v)); return r;
}
__device__ __forceinline__ uint32_t smem_u32(const void* p) {
    uint32_t a; asm("{ .reg .u64 t; cvta.to.shared.u64 t, %1; cvt.u32.u64 %0, t; }"
                    : "=r"(a) : "l"(p)); return a;
}
__device__ __forceinline__ void ldsm4(uint32_t& r0, uint32_t& r1, uint32_t& r2,
                                      uint32_t& r3, uint32_t a) {
    asm volatile("ldmatrix.sync.aligned.m8n8.x4.shared.b16 {%0,%1,%2,%3}, [%4];"
                 : "=r"(r0), "=r"(r1), "=r"(r2), "=r"(r3) : "r"(a));
}
__device__ __forceinline__ void ldsm4t(uint32_t& r0, uint32_t& r1, uint32_t& r2,
                                       uint32_t& r3, uint32_t a) {
    asm volatile("ldmatrix.sync.aligned.m8n8.x4.trans.shared.b16 {%0,%1,%2,%3}, [%4];"
                 : "=r"(r0), "=r"(r1), "=r"(r2), "=r"(r3) : "r"(a));
}
__device__ __forceinline__ void mmaH(float* c, uint32_t a0, uint32_t a1,
                                     uint32_t a2, uint32_t a3,
                                     uint32_t b0, uint32_t b1) {
    asm volatile("mma.sync.aligned.m16n8k16.row.col.f32.f16.f16.f32 "
                 "{%0,%1,%2,%3}, {%4,%5,%6,%7}, {%8,%9}, {%0,%1,%2,%3};"
                 : "+f"(c[0]), "+f"(c[1]), "+f"(c[2]), "+f"(c[3])
                 : "r"(a0), "r"(a1), "r"(a2), "r"(a3), "r"(b0), "r"(b1));
}

// single-pass fp16 GEMM: dacc[4][4] += A @ B. Warp: 16 rows x 32 cols.
__device__ __forceinline__ void gemm_H(float (*dacc)[4], uint32_t aH,
                                       uint32_t bB, int bstep)
{
#pragma unroll
    for (int kc = 0; kc < 8; ++kc) {
        uint32_t a0,a1,a2,a3;
        ldsm4(a0,a1,a2,a3, aH + kc*32);
        uint32_t bp = bB + kc*bstep;
        uint32_t b0,b1,b2,b3, b4,b5,b6,b7;
        ldsm4t(b0,b1,b2,b3, bp);
        ldsm4t(b4,b5,b6,b7, bp + 32);
        mmaH(dacc[0], a0,a1,a2,a3, b0,b1);
        mmaH(dacc[1], a0,a1,a2,a3, b2,b3);
        mmaH(dacc[2], a0,a1,a2,a3, b4,b5);
        mmaH(dacc[3], a0,a1,a2,a3, b6,b7);
    }
}

// B staging, 256-thread kernels: full 128x128 tile, 8 uint4/thread
__device__ __forceinline__ void ldB8(uint4* r, int mat, int tid) {
    const uint4* src = g_Wh[mat];
#pragma unroll
    for (int q = 0; q < 8; ++q) r[q] = src[tid + q*256];
}
__device__ __forceinline__ void stB8(__half* Bp, const uint4* r, int tid) {
#pragma unroll
    for (int q = 0; q < 8; ++q) {
        int i = tid + q*256, row = i >> 4, ch = i & 15;
        *(uint4*)(Bp + row*PITCH + ch*8) = r[q];
    }
}
// B staging, 128-thread kernels: half tile (128 rows x 64 cols = 1024 uint4).
__device__ __forceinline__ void ldB4(uint4* r, int mat, int c0u, int tid) {
    const uint4* src = g_Wh[mat];
#pragma unroll
    for (int q = 0; q < 8; ++q) {
        int i = tid + q*128, row = i >> 3, ch = i & 7;
        r[q] = src[row*16 + c0u + ch];
    }
}
__device__ __forceinline__ void stB4(__half* Bp, const uint4* r, int tid) {
#pragma unroll
    for (int q = 0; q < 8; ++q) {
        int i = tid + q*128, row = i >> 3, ch = i & 7;
        *(uint4*)(Bp + row*BPITCH + ch*8) = r[q];
    }
}

__global__ void conv_w_kernel(
    const float* __restrict__ W_i, const float* __restrict__ W_f,
    const float* __restrict__ W_o, const float* __restrict__ W_u,
    const float* __restrict__ U_i, const float* __restrict__ U_f,
    const float* __restrict__ U_o, const float* __restrict__ U_u)
{
    const float* mats[8] = { W_i, W_f, W_o, W_u, U_i, U_f, U_o, U_u };
    const float* M = mats[blockIdx.x];
    __half* dst = (__half*)&g_Wh[blockIdx.x][0];
    for (int idx = threadIdx.x; idx < 16384; idx += blockDim.x)
        dst[idx] = __float2half(M[idx]);
}

// convert one fp32 row-half (opt. pair sum) into fp16 smem
__device__ __forceinline__ void conv_row_h(__half* dh, int row, int half,
                                           const float* __restrict__ s0,
                                           const float* __restrict__ s1)
{
#pragma unroll
    for (int i = 0; i < 16; ++i) {
        float4 v = *(const float4*)(s0 + i*4);
        if (s1) {
            float4 w = *(const float4*)(s1 + i*4);
            v.x += w.x; v.y += w.y; v.z += w.z; v.w += w.w;
        }
        __half2 p0 = __floats2half2_rn(v.x, v.y);
        __half2 p1 = __floats2half2_rn(v.z, v.w);
        *(uint2*)(dh + row*PITCH + half + i*4) =
            make_uint2(*(uint32_t*)&p0, *(uint32_t*)&p1);
    }
}

#define ZERO4 { _Pragma("unroll") for (int t = 0; t < 4; ++t) \
        { dacc[t][0]=0.f; dacc[t][1]=0.f; dacc[t][2]=0.f; dacc[t][3]=0.f; } }

// ---------------------------------------------------------------------------
// Leaf: 32 leaves/block, 256 threads, 2 CTAs/SM. Gates u,i,o from x@W.
// smem: X (8704 B) + B (34816 B) = 43520 B.
// ---------------------------------------------------------------------------
__global__ void __launch_bounds__(256, 2) leaf_kernel(
    const float* __restrict__ x,
    const float* __restrict__ b_i, const float* __restrict__ b_o,
    const float* __restrict__ b_u)
{
    extern __shared__ __align__(16) __half sm[];
    __half* Xh = sm;
    __half* Bp = sm + 32*PITCH;

    const int tid = threadIdx.x;
    const int w = tid >> 5, l = tid & 31;
    const int mg = w >> 2, nh = w & 3;
    const int lr = l & 15, lc = l >> 4;
    const int qr = l >> 2, qc2 = (l & 3) * 2;
    const long np = 131071L + (long)blockIdx.x * 32;

    uint4 breg[8];
    ldB8(breg, 3, tid);                     // W_u
    if (tid < 64) {
        int row = tid >> 1, half = (tid & 1) * 64;
        conv_row_h(Xh, row, half, x + (np + row)*HH + half, nullptr);
    }
    stB8(Bp, breg, tid);
    __syncthreads();

    const uint32_t a_off = (uint32_t)((16*mg + lr)*PITCH + lc*8)*2;
    const uint32_t b_off = (uint32_t)(lr*PITCH + nh*32 + lc*8)*2;
    const uint32_t xH = smem_u32(Xh)+a_off;
    const uint32_t bB = smem_u32(Bp)+b_off;

    const long n0 = np + 16*mg + qr, n1 = n0 + 8;
    const int cbase = nh*32 + qc2;

    float dacc[4][4], cc[4][4];
#define SWAPB() do { __syncthreads(); stB8(Bp, breg, tid); __syncthreads(); } while (0)

    ldB8(breg, 0, tid);                     // W_i prefetch
    ZERO4; gemm_H(dacc, xH, bB, 16*PITCH*2);
#pragma unroll
    for (int t = 0; t < 4; ++t) {
        float2 b = *(const float2*)(b_u + cbase + t*8);
        cc[t][0]=tanhx(dacc[t][0]+b.x); cc[t][1]=tanhx(dacc[t][1]+b.y);
        cc[t][2]=tanhx(dacc[t][2]+b.x); cc[t][3]=tanhx(dacc[t][3]+b.y);
    }
    SWAPB();                                // B = W_i
    ldB8(breg, 2, tid);                     // W_o prefetch
    ZERO4; gemm_H(dacc, xH, bB, 16*PITCH*2);
#pragma unroll
    for (int t = 0; t < 4; ++t) {
        float2 b = *(const float2*)(b_i + cbase + t*8);
        cc[t][0]*=sigf(dacc[t][0]+b.x); cc[t][1]*=sigf(dacc[t][1]+b.y);
        cc[t][2]*=sigf(dacc[t][2]+b.x); cc[t][3]*=sigf(dacc[t][3]+b.y);
    }
    SWAPB();                                // B = W_o
    ZERO4; gemm_H(dacc, xH, bB, 16*PITCH*2);
#pragma unroll
    for (int t = 0; t < 4; ++t) {
        int c = cbase + t*8;
        float2 b = *(const float2*)(b_o + c);
        float h0 = sigf(dacc[t][0]+b.x)*tanhx(cc[t][0]);
        float h1 = sigf(dacc[t][1]+b.y)*tanhx(cc[t][1]);
        float h2 = sigf(dacc[t][2]+b.x)*tanhx(cc[t][2]);
        float h3 = sigf(dacc[t][3]+b.y)*tanhx(cc[t][3]);
        *(float2*)(g_c + n0*HH + c) = make_float2(cc[t][0], cc[t][1]);
        *(float2*)(g_c + n1*HH + c) = make_float2(cc[t][2], cc[t][3]);
        *(float2*)(g_h + n0*HH + c) = make_float2(h0, h1);
        *(float2*)(g_h + n1*HH + c) = make_float2(h2, h3);
    }
#undef SWAPB
}

// ---------------------------------------------------------------------------
// Tensor level (full N=128): 32 parents/block, 256 threads, 2 CTAs/SM.
// A slots: X, SUM(h0+h1), S1(h1). smem 3*8704 + 34816 = 60928 B.
// ---------------------------------------------------------------------------
__global__ void __launch_bounds__(256, 2) tlevel_kernel(
    int sl, const float* __restrict__ x,
    const float* __restrict__ b_i, const float* __restrict__ b_f,
    const float* __restrict__ b_o, const float* __restrict__ b_u)
{
    constexpr int AS = 32 * PITCH;
    extern __shared__ __align__(16) __half sm[];
    __half* Xh  = sm;
    __half* SUh = sm + AS;
    __half* S1h = sm + 2*AS;
    __half* Bp  = sm + 3*AS;

    const int tid = threadIdx.x;
    const int w = tid >> 5, l = tid & 31;
    const int mg = w >> 2, nh = w & 3;
    const int lr = l & 15, lc = l >> 4;
    const int qr = l >> 2, qc2 = (l & 3) * 2;

    const long np = (long)sl + (long)blockIdx.x * 32;
    const long cb = 2*np + 1;

    uint4 breg[8];
    ldB8(breg, 3, tid);                     // W_u
    if (tid < 192) {
        int slot = tid >> 6;                // 0=X, 1=SUM, 2=S1
        int row  = (tid & 63) >> 1;
        int half = (tid & 1) * 64;
        if (slot == 0)
            conv_row_h(Xh, row, half, x + (np + row)*HH + half, nullptr);
        else if (slot == 1)
            conv_row_h(SUh, row, half, g_h + (cb + 2*row)*HH + half,
                                       g_h + (cb + 2*row + 1)*HH + half);
        else
            conv_row_h(S1h, row, half, g_h + (cb + 2*row + 1)*HH + half, nullptr);
    }
    stB8(Bp, breg, tid);
    __syncthreads();

    const uint32_t a_off = (uint32_t)((16*mg + lr)*PITCH + lc*8)*2;
    const uint32_t b_off = (uint32_t)(lr*PITCH + nh*32 + lc*8)*2;
    const uint32_t xH  = smem_u32(Xh)+a_off;
    const uint32_t suH = smem_u32(SUh)+a_off;
    const uint32_t s1H = smem_u32(S1h)+a_off;
    const uint32_t bB  = smem_u32(Bp)+b_off;

    const long n0 = np + 16*mg + qr, n1 = n0 + 8;
    const int cbase = nh*32 + qc2;

    float dacc[4][4], cc[4][4], xf[4][4];
#define SWAPB() do { __syncthreads(); stB8(Bp, breg, tid); __syncthreads(); } while (0)
#define BSTEP (16*PITCH*2)

    // ---- u ----
    ldB8(breg, 7, tid);                     // U_u
    ZERO4; gemm_H(dacc, xH, bB, BSTEP);
    SWAPB();                                // B = U_u
    ldB8(breg, 0, tid);                     // W_i
    gemm_H(dacc, suH, bB, BSTEP);
#pragma unroll
    for (int t = 0; t < 4; ++t) {
        float2 b = *(const float2*)(b_u + cbase + t*8);
        cc[t][0]=tanhx(dacc[t][0]+b.x); cc[t][1]=tanhx(dacc[t][1]+b.y);
        cc[t][2]=tanhx(dacc[t][2]+b.x); cc[t][3]=tanhx(dacc[t][3]+b.y);
    }
    // ---- i ----
    SWAPB();                                // B = W_i
    ldB8(breg, 4, tid);                     // U_i
    ZERO4; gemm_H(dacc, xH, bB, BSTEP);
    SWAPB();                                // B = U_i
    ldB8(breg, 1, tid);                     // W_f
    gemm_H(dacc, suH, bB, BSTEP);
#pragma unroll
    for (int t = 0; t < 4; ++t) {
        float2 b = *(const float2*)(b_i + cbase + t*8);
        cc[t][0]*=sigf(dacc[t][0]+b.x); cc[t][1]*=sigf(dacc[t][1]+b.y);
        cc[t][2]*=sigf(dacc[t][2]+b.x); cc[t][3]*=sigf(dacc[t][3]+b.y);
    }
    // ---- f ----
    SWAPB();                                // B = W_f
    ldB8(breg, 5, tid);                     // U_f
    ZERO4; gemm_H(dacc, xH, bB, BSTEP);
#pragma unroll
    for (int t = 0; t < 4; ++t) {
        float2 b = *(const float2*)(b_f + cbase + t*8);
        xf[t][0]=dacc[t][0]+b.x; xf[t][1]=dacc[t][1]+b.y;
        xf[t][2]=dacc[t][2]+b.x; xf[t][3]=dacc[t][3]+b.y;
    }
    SWAPB();                                // B = U_f
    ldB8(breg, 2, tid);                     // W_o
    ZERO4; gemm_H(dacc, s1H, bB, BSTEP);               // G1 = h1 @ U_f
#pragma unroll
    for (int t = 0; t < 4; ++t) {                      // f1 with child1 cell
        int c = cbase + t*8;
        float2 ca = *(const float2*)(g_c + (2*n0+2)*HH + c);
        float2 cbv = *(const float2*)(g_c + (2*n1+2)*HH + c);
        cc[t][0]+=sigf(dacc[t][0]+xf[t][0])*ca.x;
        cc[t][1]+=sigf(dacc[t][1]+xf[t][1])*ca.y;
        cc[t][2]+=sigf(dacc[t][2]+xf[t][2])*cbv.x;
        cc[t][3]+=sigf(dacc[t][3]+xf[t][3])*cbv.y;
        dacc[t][0]=-dacc[t][0]; dacc[t][1]=-dacc[t][1];
        dacc[t][2]=-dacc[t][2]; dacc[t][3]=-dacc[t][3];
    }
    gemm_H(dacc, suH, bB, BSTEP);                      // Gsum - G1 = h0 @ U_f
#pragma unroll
    for (int t = 0; t < 4; ++t) {                      // f0 with child0 cell
        int c = cbase + t*8;
        float2 ca = *(const float2*)(g_c + (2*n0+1)*HH + c);
        float2 cbv = *(const float2*)(g_c + (2*n1+1)*HH + c);
        cc[t][0]+=sigf(dacc[t][0]+xf[t][0])*ca.x;
        cc[t][1]+=sigf(dacc[t][1]+xf[t][1])*ca.y;
        cc[t][2]+=sigf(dacc[t][2]+xf[t][2])*cbv.x;
        cc[t][3]+=sigf(dacc[t][3]+xf[t][3])*cbv.y;
    }
    // ---- o + store ----
    SWAPB();                                // B = W_o
    ldB8(breg, 6, tid);                     // U_o
    ZERO4; gemm_H(dacc, xH, bB, BSTEP);
    SWAPB();                                // B = U_o
    gemm_H(dacc, suH, bB, BSTEP);
#pragma unroll
    for (int t = 0; t < 4; ++t) {
        int c = cbase + t*8;
        float2 b = *(const float2*)(b_o + c);
        float h0 = sigf(dacc[t][0]+b.x)*tanhx(cc[t][0]);
        float h1 = sigf(dacc[t][1]+b.y)*tanhx(cc[t][1]);
        float h2 = sigf(dacc[t][2]+b.x)*tanhx(cc[t][2]);
        float h3 = sigf(dacc[t][3]+b.y)*tanhx(cc[t][3]);
        *(float2*)(g_c + n0*HH + c) = make_float2(cc[t][0], cc[t][1]);
        *(float2*)(g_c + n1*HH + c) = make_float2(cc[t][2], cc[t][3]);
        *(float2*)(g_h + n0*HH + c) = make_float2(h0, h1);
        *(float2*)(g_h + n1*HH + c) = make_float2(h2, h3);
    }
#undef SWAPB
#undef BSTEP
}

// ---------------------------------------------------------------------------
// Column-split tensor level (N=64): 32 parents/block, 128 threads, 4 CTAs/SM.
// bid>>1 selects parents, bid&1 selects column half.
// smem: 3*8704 + 18432 = 44544 B.
// ---------------------------------------------------------------------------
__global__ void __launch_bounds__(128, 4) tlevel64_kernel(
    int sl, const float* __restrict__ x,
    const float* __restrict__ b_i, const float* __restrict__ b_f,
    const float* __restrict__ b_o, const float* __restrict__ b_u)
{
    constexpr int AS = 32 * PITCH;
    extern __shared__ __align__(16) __half sm[];
    __half* Xh  = sm;
    __half* SUh = sm + AS;
    __half* S1h = sm + 2*AS;
    __half* Bp  = sm + 3*AS;

    const int tid = threadIdx.x;
    const int w = tid >> 5, l = tid & 31;
    const int mg = w >> 1, nh = w & 1;
    const int lr = l & 15, lc = l >> 4;
    const int qr = l >> 2, qc2 = (l & 3) * 2;

    const int  c0  = (blockIdx.x & 1) * 64;      // column half
    const int  c0u = (blockIdx.x & 1) * 8;       // uint4 offset in weight rows
    const long np  = (long)sl + (long)(blockIdx.x >> 1) * 32;
    const long cb  = 2*np + 1;

    uint4 breg[8];
    ldB4(breg, 3, c0u, tid);                // W_u half
    for (int j = tid; j < 192; j += 128) {
        int slot = j >> 6;
        int row  = (j & 63) >> 1;
        int half = (j & 1) * 64;
        if (slot == 0)
            conv_row_h(Xh, row, half, x + (np + row)*HH + half, nullptr);
        else if (slot == 1)
            conv_row_h(SUh, row, half, g_h + (cb + 2*row)*HH + half,
                                       g_h + (cb + 2*row + 1)*HH + half);
        else
            conv_row_h(S1h, row, half, g_h + (cb + 2*row + 1)*HH + half, nullptr);
    }
    stB4(Bp, breg, tid);
    __syncthreads();

    const uint32_t a_off = (uint32_t)((16*mg + lr)*PITCH + lc*8)*2;
    const uint32_t b_off = (uint32_t)(lr*BPITCH + nh*32 + lc*8)*2;
    const uint32_t xH  = smem_u32(Xh)+a_off;
    const uint32_t suH = smem_u32(SUh)+a_off;
    const uint32_t s1H = smem_u32(S1h)+a_off;
    const uint32_t bB  = smem_u32(Bp)+b_off;

    const long n0 = np + 16*mg + qr, n1 = n0 + 8;
    const int cbase = c0 + nh*32 + qc2;

    float dacc[4][4], cc[4][4], xf[4][4];
#define SWAPB() do { __syncthreads(); stB4(Bp, breg, tid); __syncthreads(); } while (0)
#define BSTEP (16*BPITCH*2)

    // ---- u ----
    ldB4(breg, 7, c0u, tid);                // U_u
    ZERO4; gemm_H(dacc, xH, bB, BSTEP);
    SWAPB();
    ldB4(breg, 0, c0u, tid);                // W_i
    gemm_H(dacc, suH, bB, BSTEP);
#pragma unroll
    for (int t = 0; t < 4; ++t) {
        float2 b = *(const float2*)(b_u + cbase + t*8);
        cc[t][0]=tanhx(dacc[t][0]+b.x); cc[t][1]=tanhx(dacc[t][1]+b.y);
        cc[t][2]=tanhx(dacc[t][2]+b.x); cc[t][3]=tanhx(dacc[t][3]+b.y);
    }
    // ---- i ----
    SWAPB();
    ldB4(breg, 4, c0u, tid);                // U_i
    ZERO4; gemm_H(dacc, xH, bB, BSTEP);
    SWAPB();
    ldB4(breg, 1, c0u, tid);                // W_f
    gemm_H(dacc, suH, bB, BSTEP);
#pragma unroll
    for (int t = 0; t < 4; ++t) {
        float2 b = *(const float2*)(b_i + cbase + t*8);
        cc[t][0]*=sigf(dacc[t][0]+b.x); cc[t][1]*=sigf(dacc[t][1]+b.y);
        cc[t][2]*=sigf(dacc[t][2]+b.x); cc[t][3]*=sigf(dacc[t][3]+b.y);
    }
    // ---- f ----
    SWAPB();
    ldB4(breg, 5, c0u, tid);                // U_f
    ZERO4; gemm_H(dacc, xH, bB, BSTEP);
#pragma unroll
    for (int t = 0; t < 4; ++t) {
        float2 b = *(const float2*)(b_f + cbase + t*8);
        xf[t][0]=dacc[t][0]+b.x; xf[t][1]=dacc[t][1]+b.y;
        xf[t][2]=dacc[t][2]+b.x; xf[t][3]=dacc[t][3]+b.y;
    }
    SWAPB();
    ldB4(breg, 2, c0u, tid);                // W_o
    ZERO4; gemm_H(dacc, s1H, bB, BSTEP);               // G1 = h1 @ U_f
#pragma unroll
    for (int t = 0; t < 4; ++t) {
        int c = cbase + t*8;
        float2 ca = *(const float2*)(g_c + (2*n0+2)*HH + c);
        float2 cbv = *(const float2*)(g_c + (2*n1+2)*HH + c);
        cc[t][0]+=sigf(dacc[t][0]+xf[t][0])*ca.x;
        cc[t][1]+=sigf(dacc[t][1]+xf[t][1])*ca.y;
        cc[t][2]+=sigf(dacc[t][2]+xf[t][2])*cbv.x;
        cc[t][3]+=sigf(dacc[t][3]+xf[t][3])*cbv.y;
        dacc[t][0]=-dacc[t][0]; dacc[t][1]=-dacc[t][1];
        dacc[t][2]=-dacc[t][2]; dacc[t][3]=-dacc[t][3];
    }
    gemm_H(dacc, suH, bB, BSTEP);                      // Gsum - G1 = h0 @ U_f
#pragma unroll
    for (int t = 0; t < 4; ++t) {
        int c = cbase + t*8;
        float2 ca = *(const float2*)(g_c + (2*n0+1)*HH + c);
        float2 cbv = *(const float2*)(g_c + (2*n1+1)*HH + c);
        cc[t][0]+=sigf(dacc[t][0]+xf[t][0])*ca.x;
        cc[t][1]+=sigf(dacc[t][1]+xf[t][1])*ca.y;
        cc[t][2]+=sigf(dacc[t][2]+xf[t][2])*cbv.x;
        cc[t][3]+=sigf(dacc[t][3]+xf[t][3])*cbv.y;
    }
    // ---- o + store ----
    SWAPB();
    ldB4(breg, 6, c0u, tid);                // U_o
    ZERO4; gemm_H(dacc, xH, bB, BSTEP);
    SWAPB();
    gemm_H(dacc, suH, bB, BSTEP);
#pragma unroll
    for (int t = 0; t < 4; ++t) {
        int c = cbase + t*8;
        float2 b = *(const float2*)(b_o + c);
        float h0 = sigf(dacc[t][0]+b.x)*tanhx(cc[t][0]);
        float h1 = sigf(dacc[t][1]+b.y)*tanhx(cc[t][1]);
        float h2 = sigf(dacc[t][2]+b.x)*tanhx(cc[t][2]);
        float h3 = sigf(dacc[t][3]+b.y)*tanhx(cc[t][3]);
        *(float2*)(g_c + n0*HH + c) = make_float2(cc[t][0], cc[t][1]);
        *(float2*)(g_c + n1*HH + c) = make_float2(cc[t][2], cc[t][3]);
        *(float2*)(g_h + n0*HH + c) = make_float2(h0, h1);
        *(float2*)(g_h + n1*HH + c) = make_float2(h2, h3);
    }
#undef SWAPB
#undef BSTEP
}

// ---------------------------------------------------------------------------
// Small levels (nl <= 256): one parent/block, 512 threads, 9 k-split matvecs.
// ---------------------------------------------------------------------------
__global__ void __launch_bounds__(512) small_level_kernel(
    int sl, const float* __restrict__ x,
    const float* __restrict__ W_i, const float* __restrict__ b_i, const float* __restrict__ U_i,
    const float* __restrict__ W_f, const float* __restrict__ b_f, const float* __restrict__ U_f,
    const float* __restrict__ W_o, const float* __restrict__ b_o, const float* __restrict__ U_o,
    const float* __restrict__ W_u, const float* __restrict__ b_u, const float* __restrict__ U_u)
{
    extern __shared__ float smf[];
    float* hs   = smf;              // [h~ | h0 | h1 | x] x 128
    float* part = smf + 512;        // [9][4][128]

    const int t = threadIdx.x;
    const long node = sl + blockIdx.x;
    const long ch0  = 2*node + 1;

    if (t < 128) {
        float h0 = g_h[ch0*HH + t];
        float h1 = g_h[(ch0+1)*HH + t];
        hs[128+t] = h0; hs[256+t] = h1; hs[t] = h0 + h1;
        hs[384+t] = x[node*HH + t];
    }
    __syncthreads();

    const int col = t & 127;
    const int q   = t >> 7;
    const int kb  = q * 32;

#define JOB(J, S, M) { float av = 0.f; const float* s = hs + (S)*128;          \
        _Pragma("unroll 8")                                                    \
        for (int k = 0; k < 32; ++k) av += s[kb+k] * (M)[(kb+k)*HH + col];     \
        part[((J)*4 + q)*128 + col] = av; }
    JOB(0, 0, U_i) JOB(1, 0, U_o) JOB(2, 0, U_u)
    JOB(3, 1, U_f) JOB(4, 2, U_f)
    JOB(5, 3, W_i) JOB(6, 3, W_f) JOB(7, 3, W_o) JOB(8, 3, W_u)
#undef JOB
    __syncthreads();

    if (t < 128) {
#define SUMP(J) (part[((J)*4+0)*128+t] + part[((J)*4+1)*128+t] + \
                 part[((J)*4+2)*128+t] + part[((J)*4+3)*128+t])
        float yi  = SUMP(0), yo = SUMP(1), yu = SUMP(2);
        float yf0 = SUMP(3), yf1 = SUMP(4);
        float xi  = SUMP(5) + b_i[t];
        float xfv = SUMP(6) + b_f[t];
        float xo  = SUMP(7) + b_o[t];
        float xu  = SUMP(8) + b_u[t];
#undef SUMP
        float c = sigf(xi+yi)*tanhx(xu+yu)
                + sigf(xfv+yf0)*g_c[ch0*HH+t] + sigf(xfv+yf1)*g_c[(ch0+1)*HH+t];
        g_c[node*HH+t] = c;
        g_h[node*HH+t] = sigf(xo+yo)*tanhx(c);
    }
}

__global__ void out_kernel(float* __restrict__ out)
{
    int t = threadIdx.x;
    out[t] = (t < 128) ? g_h[t] : g_c[t - 128];
}

// ---------------------------------------------------------------------------
extern "C" void kernel_launch(void* const* d_in, const int* in_sizes, int n_in,
                              void* d_out, int out_size)
{
    const float* x   = (const float*)d_in[0];
    const float* W_i = (const float*)d_in[1];
    const float* b_i = (const float*)d_in[2];
    const float* U_i = (const float*)d_in[3];
    const float* W_f = (const float*)d_in[4];
    const float* b_f = (const float*)d_in[5];
    const float* U_f = (const float*)d_in[6];
    const float* W_o = (const float*)d_in[7];
    const float* b_o = (const float*)d_in[8];
    const float* U_o = (const float*)d_in[9];
    const float* W_u = (const float*)d_in[10];
    const float* b_u = (const float*)d_in[11];
    const float* U_u = (const float*)d_in[12];

    const int SMEM_T   = (3*32*PITCH + 128*PITCH) * 2;   // 60928
    const int SMEM_T64 = 3*32*PITCH*2 + 128*BPITCH*2;    // 44544
    const int SMEM_L   = (32*PITCH + 128*PITCH) * 2;     // 43520
    const int SMEM_S   = (512 + 9*4*128) * 4;
    cudaFuncSetAttribute(tlevel_kernel,   cudaFuncAttributeMaxDynamicSharedMemorySize, SMEM_T);
    cudaFuncSetAttribute(tlevel64_kernel, cudaFuncAttributeMaxDynamicSharedMemorySize, SMEM_T64);
    cudaFuncSetAttribute(leaf_kernel,     cudaFuncAttributeMaxDynamicSharedMemorySize, SMEM_L);
    cudaFuncSetAttribute(small_level_kernel, cudaFuncAttributeMaxDynamicSharedMemorySize, SMEM_S);

    conv_w_kernel<<<8, 256>>>(W_i, W_f, W_o, W_u, U_i, U_f, U_o, U_u);

    leaf_kernel<<<131072 / 32, 256, SMEM_L>>>(x, b_i, b_o, b_u);

    for (int l = DEPTH - 1; l >= 0; --l) {
        int nl = 1 << l;
        int sl = nl - 1;
        if (nl >= 16384)
            tlevel_kernel<<<nl / 32, 256, SMEM_T>>>(sl, x, b_i, b_f, b_o, b_u);
        else if (nl >= 512)
            tlevel64_kernel<<<(nl / 32) * 2, 128, SMEM_T64>>>(sl, x, b_i, b_f, b_o, b_u);
        else
            small_level_kernel<<<nl, 512, SMEM_S>>>(sl, x,
                W_i, b_i, U_i, W_f, b_f, U_f, W_o, b_o, U_o, W_u, b_u, U_u);
    }

    out_kernel<<<1, 256>>>((float*)d_out);
}